// round 13
// baseline (speedup 1.0000x reference)
#include <cuda_runtime.h>
#include <cuda_fp16.h>
#include <mma.h>
#include <math.h>

using namespace nvcuda;

#define N_NODES 50000
#define E_EDGES 800000
#define DIM 128
#define NHEAD 8
#define HDIM 16
#define LN_EPS 1e-5f
#define FULLMASK 0xFFFFFFFFu
#define N_TILES 196                 // tiles of 256 nodes per graph

// Scratch (static __device__ arrays: allocation-free per harness rules)
__device__ __half2 d_xh[N_NODES * 64];    // fp16 gather input, pass 1 (feat*norm_src1)
__device__ __half2 d_xh2[N_NODES * 64];   // fp16 gather input, pass 2 (attended*norm_src2)
__device__ int    d_deg[4 * N_NODES];     // [src1 | dst1 | src2 | dst2] degrees
__device__ float  d_norm[4 * N_NODES];    // rsqrt norms, same layout
__device__ int    d_off[2 * N_NODES];     // CSR row offsets [dst1 | dst2]
__device__ int    d_csr[2 * E_EDGES];     // CSR column (source-node) ids [g1 | g2]
__device__ unsigned short d_rank[2 * E_EDGES];  // edge rank within its dst row
__device__ unsigned long long d_look[2 * N_TILES];  // lookback: status(hi32)|value(lo32)
__device__ __half d_wh[2 * DIM * DIM];    // fp16 W1 | W2

// ---------------------------------------------------------------------------
// Degrees + per-edge dst ranks. The dst-counter atomicAdd RETURN is exactly
// the edge's rank within its CSR row -> later scatter needs no atomics.
// src counters remain non-returning (compile to RED).
// ---------------------------------------------------------------------------
__global__ void degrees_kernel(const int* __restrict__ s1, const int* __restrict__ t1,
                               const int* __restrict__ s2, const int* __restrict__ t2) {
    int i = blockIdx.x * blockDim.x + threadIdx.x;
    if (i >= E_EDGES) return;
    atomicAdd(&d_deg[0 * N_NODES + s1[i]], 1);
    atomicAdd(&d_deg[2 * N_NODES + s2[i]], 1);
    int p1 = atomicAdd(&d_deg[1 * N_NODES + t1[i]], 1);
    int p2 = atomicAdd(&d_deg[3 * N_NODES + t2[i]], 1);
    d_rank[i] = (unsigned short)p1;
    d_rank[E_EDGES + i] = (unsigned short)p2;
}

// ---------------------------------------------------------------------------
// Fused norms + CSR offsets via decoupled lookback. grid = 2*N_TILES (392) x 256.
// ---------------------------------------------------------------------------
__global__ void __launch_bounds__(256) scan_norm_kernel() {
    __shared__ int ws[8];
    __shared__ int sprefix;
    int bid = blockIdx.x;
    int g = bid / N_TILES, b = bid % N_TILES;
    int t = threadIdx.x, lane = t & 31, w = t >> 5;

    // norms for all 4 segments (grid-stride; 2 iterations/thread)
    for (int i = bid * 256 + t; i < 4 * N_NODES; i += 2 * N_TILES * 256) {
        int d = d_deg[i];
        d_norm[i] = (d > 0) ? rsqrtf((float)d) : 0.f;
    }

    // block-local inclusive scan of this tile's dst degrees
    int degoff = (g ? 3 : 1) * N_NODES;
    int n = b * 256 + t;
    int v = (n < N_NODES) ? d_deg[degoff + n] : 0;
    int x = v;
#pragma unroll
    for (int o = 1; o < 32; o <<= 1) {
        int y = __shfl_up_sync(FULLMASK, x, o);
        if (lane >= o) x += y;
    }
    if (lane == 31) ws[w] = x;
    __syncthreads();
    if (t < 8) {
        int s = ws[t];
#pragma unroll
        for (int o = 1; o < 8; o <<= 1) {
            int y = __shfl_up_sync(0xFFu, s, o);
            if (t >= o) s += y;
        }
        ws[t] = s;
    }
    __syncthreads();
    int incl = x + ((w > 0) ? ws[w - 1] : 0);
    int total = ws[7];                       // block total

    // warp 0: publish aggregate, lookback, publish inclusive
    if (w == 0) {
        if (lane == 0) {
            unsigned long long agg = (1ULL << 32) | (unsigned)total;
            __threadfence();
            atomicExch(&d_look[bid], agg);
        }
        __syncwarp();
        int running = 0;
        if (b == 0) {
            if (lane == 0) {
                unsigned long long inc = (2ULL << 32) | (unsigned)total;
                __threadfence();
                atomicExch(&d_look[bid], inc);
                sprefix = 0;
            }
        } else {
            int jend = b - 1;
            bool done = false;
            while (!done) {
                int j = jend - lane;
                unsigned long long e = (j >= 0)
                    ? atomicAdd(&d_look[g * N_TILES + j], 0ULL)
                    : (2ULL << 32);
                unsigned st = (unsigned)(e >> 32);
                if (__ballot_sync(FULLMASK, st == 0)) continue;   // window not ready
                unsigned ball2 = __ballot_sync(FULLMASK, (st == 2) && (j >= 0));
                int firstlane = ball2 ? (__ffs(ball2) - 1) : 32;
                int val = ((lane <= firstlane) && (j >= 0)) ? (int)(unsigned)e : 0;
#pragma unroll
                for (int o = 16; o > 0; o >>= 1) val += __shfl_down_sync(FULLMASK, val, o);
                if (lane == 0) running += val;
                if (firstlane < 32) done = true;
                else { jend -= 32; if (jend < 0) done = true; }
            }
            if (lane == 0) {
                unsigned long long inc = (2ULL << 32) | (unsigned)(running + total);
                __threadfence();
                atomicExch(&d_look[bid], inc);
                sprefix = running;
            }
        }
    }
    __syncthreads();
    if (n < N_NODES) {
        d_off[g * N_NODES + n] = sprefix + incl - v;   // exclusive
    }
}

// ---------------------------------------------------------------------------
// Atomic-free CSR scatter (off[t] + precomputed rank) + feature fp16 convert
// + weight fp16 convert (W work appended; overlaps the latency-bound phases).
// ---------------------------------------------------------------------------
#define SCAT_BLOCKS ((2 * E_EDGES) / 256)        // 6250
#define CONV_BLOCKS ((N_NODES * 32 + 255) / 256) // 6250
#define WCONV_BLOCKS ((2 * DIM * DIM / 4) / 256) // 32
__global__ void scatter_convert_kernel(const int* __restrict__ s1, const int* __restrict__ t1,
                                       const int* __restrict__ s2, const int* __restrict__ t2,
                                       const float* __restrict__ feat,
                                       const float* __restrict__ W1,
                                       const float* __restrict__ W2) {
    int bid = blockIdx.x;
    if (bid < SCAT_BLOCKS) {
        int i = bid * 256 + threadIdx.x;
        if (i < E_EDGES) {
            int p = d_off[0 * N_NODES + t1[i]] + (int)d_rank[i];
            d_csr[p] = s1[i];
        } else {
            int e = i - E_EDGES;
            int p = d_off[1 * N_NODES + t2[e]] + (int)d_rank[E_EDGES + e];
            d_csr[E_EDGES + p] = s2[e];
        }
    } else if (bid < SCAT_BLOCKS + CONV_BLOCKS) {
        int i = (bid - SCAT_BLOCKS) * 256 + threadIdx.x;
        if (i >= N_NODES * 32) return;
        int n = i >> 5, c4 = i & 31;
        float nm = d_norm[n];                       // src1 norms at offset 0
        float4 v = ((const float4*)feat)[i];
        __half2 h0 = __floats2half2_rn(v.x * nm, v.y * nm);
        __half2 h1 = __floats2half2_rn(v.z * nm, v.w * nm);
        uint2 st; st.x = *(unsigned*)&h0; st.y = *(unsigned*)&h1;
        *(uint2*)(d_xh + n * 64 + c4 * 2) = st;
    } else {
        int i = (bid - SCAT_BLOCKS - CONV_BLOCKS) * 256 + threadIdx.x;  // float4 idx
        const float* W = (i < 4096) ? W1 : W2;
        int li = (i < 4096) ? i : i - 4096;
        float4 v = ((const float4*)W)[li];
        __half2 h0 = __floats2half2_rn(v.x, v.y);
        __half2 h1 = __floats2half2_rn(v.z, v.w);
        uint2 st; st.x = *(unsigned*)&h0; st.y = *(unsigned*)&h1;
        *(uint2*)(d_wh + i * 4) = st;
    }
}

// ---------------------------------------------------------------------------
// Fused gather + tensor-core GEMM.
// smem layout (bytes):
//   [0, 34816)       Ws_h: half[128][136]  -- later aliased by C (fp32 64x132)
//   [34816, 52224)   As_h: half[64][136]
//   [52224, 54272)   red:  float[512]
// ---------------------------------------------------------------------------
#define WS_H_OFF 0
#define AS_H_OFF 34816
#define RED_OFF  52224
#define SMEM_BYTES 54272
#define A_LDH 136
#define C_LDF 132

__device__ __forceinline__ void acc_half16(float4& a0, float4& a1, uint4 r) {
    __half2 h0 = *(__half2*)&r.x;
    __half2 h1 = *(__half2*)&r.y;
    __half2 h2 = *(__half2*)&r.z;
    __half2 h3 = *(__half2*)&r.w;
    float2 f0 = __half22float2(h0);
    float2 f1 = __half22float2(h1);
    float2 f2 = __half22float2(h2);
    float2 f3 = __half22float2(h3);
    a0.x += f0.x; a0.y += f0.y; a0.z += f1.x; a0.w += f1.y;
    a1.x += f2.x; a1.y += f2.y; a1.z += f3.x; a1.w += f3.y;
}

__device__ __forceinline__ void gather_gemm_mainloop(char* smem, int graph, int w_off,
                                                     const __half2* __restrict__ base,
                                                     const float* __restrict__ bias,
                                                     int norm_off, int m0) {
    __half* Ws = (__half*)(smem + WS_H_OFF);
    __half* As = (__half*)(smem + AS_H_OFF);
    float*  C  = (float*)smem;
    int tid = threadIdx.x;

    // --- Phase 1: W fp16 (128x128) -> smem ld=136 (uint4 copies) ---
    const __half* Wh = d_wh + w_off;
#pragma unroll
    for (int j = 0; j < 8; j++) {
        int idx = j * 256 + tid;            // uint4 index, 2048 total
        int row = idx >> 4, c8 = idx & 15;  // 16 uint4 per row (128 halves)
        uint4 v = ((const uint4*)Wh)[idx];
        *(uint4*)(Ws + row * A_LDH + c8 * 8) = v;
    }

    // --- Phase 2: CSR gather directly into fp16 A smem ---
    // 2 accumulator pairs (register diet), 4 independent loads in flight.
    int hw = tid >> 4;                       // half-warp 0..15
    int lane16 = tid & 15;
    unsigned hmask = 0xFFFFu << (tid & 16);
    int degseg = (graph == 0 ? 1 : 3) * N_NODES;
    const int* csr = d_csr + graph * E_EDGES;

#pragma unroll
    for (int k = 0; k < 4; k++) {
        int n_local = k * 16 + hw;
        int gnode = m0 + n_local;
        float4 a00 = make_float4(0.f,0.f,0.f,0.f), a01 = make_float4(0.f,0.f,0.f,0.f);
        float4 a10 = make_float4(0.f,0.f,0.f,0.f), a11 = make_float4(0.f,0.f,0.f,0.f);
        float nm = 0.f;
        if (gnode < N_NODES) {
            nm = d_norm[norm_off + gnode];
            int beg = d_off[graph * N_NODES + gnode];
            int cnt = d_deg[degseg + gnode];
            for (int j0 = 0; j0 < cnt; j0 += 16) {
                int m = min(16, cnt - j0);
                int s_l = (lane16 < m) ? csr[beg + j0 + lane16] : 0;
                int jj = 0;
                for (; jj + 3 < m; jj += 4) {
                    int sA = __shfl_sync(hmask, s_l, jj,     16);
                    int sB = __shfl_sync(hmask, s_l, jj + 1, 16);
                    int sC = __shfl_sync(hmask, s_l, jj + 2, 16);
                    int sD = __shfl_sync(hmask, s_l, jj + 3, 16);
                    uint4 rA = *(const uint4*)(base + sA * 64 + lane16 * 4);
                    uint4 rB = *(const uint4*)(base + sB * 64 + lane16 * 4);
                    uint4 rC = *(const uint4*)(base + sC * 64 + lane16 * 4);
                    uint4 rD = *(const uint4*)(base + sD * 64 + lane16 * 4);
                    acc_half16(a00, a01, rA);
                    acc_half16(a10, a11, rB);
                    acc_half16(a00, a01, rC);
                    acc_half16(a10, a11, rD);
                }
                for (; jj < m; jj++) {
                    int sA = __shfl_sync(hmask, s_l, jj, 16);
                    uint4 rA = *(const uint4*)(base + sA * 64 + lane16 * 4);
                    acc_half16(a00, a01, rA);
                }
            }
        }
        a00.x += a10.x; a00.y += a10.y; a00.z += a10.z; a00.w += a10.w;
        a01.x += a11.x; a01.y += a11.y; a01.z += a11.z; a01.w += a11.w;
        __half2 h0 = __floats2half2_rn(a00.x * nm, a00.y * nm);
        __half2 h1 = __floats2half2_rn(a00.z * nm, a00.w * nm);
        __half2 h2 = __floats2half2_rn(a01.x * nm, a01.y * nm);
        __half2 h3 = __floats2half2_rn(a01.z * nm, a01.w * nm);
        uint4 st;
        st.x = *(unsigned int*)&h0;
        st.y = *(unsigned int*)&h1;
        st.z = *(unsigned int*)&h2;
        st.w = *(unsigned int*)&h3;
        *(uint4*)(As + n_local * A_LDH + lane16 * 8) = st;
    }
    __syncthreads();

    // --- Phase 3: wmma mainloop ---
    int wid = tid >> 5;
    int wm = wid & 3;       // 4 row-groups of 16
    int wn = wid >> 2;      // 2 col-groups of 64

    wmma::fragment<wmma::accumulator, 16, 16, 16, float> acc[4];
#pragma unroll
    for (int n = 0; n < 4; n++) wmma::fill_fragment(acc[n], 0.f);

#pragma unroll
    for (int k = 0; k < 8; k++) {
        wmma::fragment<wmma::matrix_a, 16, 16, 16, __half, wmma::row_major> fa;
        wmma::load_matrix_sync(fa, As + (wm * 16) * A_LDH + k * 16, A_LDH);
#pragma unroll
        for (int n = 0; n < 4; n++) {
            wmma::fragment<wmma::matrix_b, 16, 16, 16, __half, wmma::row_major> fb;
            wmma::load_matrix_sync(fb, Ws + (k * 16) * A_LDH + wn * 64 + n * 16, A_LDH);
            wmma::mma_sync(acc[n], fa, fb, acc[n]);
        }
    }
    __syncthreads();   // done reading Ws/As; C aliases Ws region

#pragma unroll
    for (int n = 0; n < 4; n++)
        wmma::store_matrix_sync(C + (wm * 16) * C_LDF + wn * 64 + n * 16,
                                acc[n], C_LDF, wmma::mem_row_major);
    __syncthreads();

    // bias + ReLU in place
#pragma unroll
    for (int j = 0; j < 8; j++) {
        int idx = j * 256 + tid;
        int r = idx >> 5, c4 = idx & 31;
        float4 v = *(float4*)(C + r * C_LDF + c4 * 4);
        float4 bv = ((const float4*)bias)[c4];
        v.x = fmaxf(v.x + bv.x, 0.f);
        v.y = fmaxf(v.y + bv.y, 0.f);
        v.z = fmaxf(v.z + bv.z, 0.f);
        v.w = fmaxf(v.w + bv.w, 0.f);
        *(float4*)(C + r * C_LDF + c4 * 4) = v;
    }
    __syncthreads();
}

// gather(g1, from d_xh) + GEMM1 + attention + src2-norm prescale -> d_xh2 (fp16)
__global__ void __launch_bounds__(256)
gemm_att_kernel(const float* __restrict__ bias) {
    extern __shared__ char smc[];
    float* As  = (float*)smc;                 // C tile
    float* red = (float*)(smc + RED_OFF);
    int tid = threadIdx.x;
    int m0 = blockIdx.x * 64;

    gather_gemm_mainloop(smc, 0, 0, d_xh, bias, 1 * N_NODES, m0);

    {
        int row = tid >> 2, q = tid & 3;
#pragma unroll
        for (int hh = 0; hh < 2; hh++) {
            int head = q * 2 + hh;
            float s = 0.f;
#pragma unroll
            for (int c = 0; c < HDIM; c++) {
                float v = As[row * C_LDF + head * HDIM + c];
                s += v * v;
            }
            red[row * 8 + head] = s * 0.25f;   // / sqrt(HD)=4
        }
    }
    __syncthreads();
    if ((tid & 3) == 0) {
        int row = tid >> 2;
        float sc[8], mx = -1e30f;
#pragma unroll
        for (int h = 0; h < 8; h++) { sc[h] = red[row * 8 + h]; mx = fmaxf(mx, sc[h]); }
        float sum = 0.f;
#pragma unroll
        for (int h = 0; h < 8; h++) { sc[h] = expf(sc[h] - mx); sum += sc[h]; }
        float inv = 1.f / sum;
#pragma unroll
        for (int h = 0; h < 8; h++) red[row * 8 + h] = sc[h] * inv;
    }
    __syncthreads();
    {
        int row = tid >> 2, q = tid & 3;
        int g = m0 + row;
        if (g < N_NODES) {
            float nm = d_norm[2 * N_NODES + g];   // src2 norm prescale
#pragma unroll
            for (int j = 0; j < 8; j++) {
                int col = q * 32 + j * 4;
                float p = red[row * 8 + (col >> 4)] * nm;
                float4 v = *(float4*)(As + row * C_LDF + col);
                __half2 h0 = __floats2half2_rn(v.x * p, v.y * p);
                __half2 h1 = __floats2half2_rn(v.z * p, v.w * p);
                uint2 st;
                st.x = *(unsigned int*)&h0;
                st.y = *(unsigned int*)&h1;
                *(uint2*)(d_xh2 + g * 64 + (col >> 1)) = st;   // double buffer: no WAR race
            }
        }
    }
}

// gather(g2, from d_xh2) + GEMM2 + LayerNorm -> out
__global__ void __launch_bounds__(256)
gemm_ln_kernel(const float* __restrict__ bias,
               const float* __restrict__ gamma, const float* __restrict__ beta,
               float* __restrict__ out) {
    extern __shared__ char smc[];
    float* As  = (float*)smc;                 // C tile
    float* red = (float*)(smc + RED_OFF);
    int tid = threadIdx.x;
    int m0 = blockIdx.x * 64;

    gather_gemm_mainloop(smc, 1, DIM * DIM, d_xh2, bias, 3 * N_NODES, m0);

    {
        int row = tid >> 2, q = tid & 3;
        float s = 0.f, s2 = 0.f;
#pragma unroll
        for (int c = 0; c < 32; c++) {
            float v = As[row * C_LDF + q * 32 + c];
            s += v; s2 += v * v;
        }
        red[row * 8 + q] = s;
        red[row * 8 + 4 + q] = s2;
    }
    __syncthreads();
    if ((tid & 3) == 0) {
        int row = tid >> 2;
        float s = red[row * 8 + 0] + red[row * 8 + 1] + red[row * 8 + 2] + red[row * 8 + 3];
        float s2 = red[row * 8 + 4] + red[row * 8 + 5] + red[row * 8 + 6] + red[row * 8 + 7];
        float mu = s * (1.f / 128.f);
        float var = s2 * (1.f / 128.f) - mu * mu;
        red[row * 8 + 0] = mu;
        red[row * 8 + 1] = rsqrtf(var + LN_EPS);
    }
    __syncthreads();
    {
        int row = tid >> 2, q = tid & 3;
        int g = m0 + row;
        if (g < N_NODES) {
            float mu = red[row * 8 + 0];
            float rstd = red[row * 8 + 1];
#pragma unroll
            for (int j = 0; j < 8; j++) {
                int col = q * 32 + j * 4;
                float4 v = *(float4*)(As + row * C_LDF + col);
                float4 gm = ((const float4*)gamma)[col >> 2];
                float4 bt = ((const float4*)beta)[col >> 2];
                v.x = (v.x - mu) * rstd * gm.x + bt.x;
                v.y = (v.y - mu) * rstd * gm.y + bt.y;
                v.z = (v.z - mu) * rstd * gm.z + bt.z;
                v.w = (v.w - mu) * rstd * gm.w + bt.w;
                *(float4*)(out + g * DIM + col) = v;
            }
        }
    }
}

// ---------------------------------------------------------------------------
extern "C" void kernel_launch(void* const* d_in, const int* in_sizes, int n_in,
                              void* d_out, int out_size) {
    const float* feat  = (const float*)d_in[0];
    const int*   src1  = (const int*)d_in[1];
    const int*   dst1  = (const int*)d_in[2];
    const int*   src2  = (const int*)d_in[3];
    const int*   dst2  = (const int*)d_in[4];
    const float* W1    = (const float*)d_in[5];
    const float* b1    = (const float*)d_in[6];
    const float* W2    = (const float*)d_in[7];
    const float* b2    = (const float*)d_in[8];
    const float* gamma = (const float*)d_in[9];
    const float* beta  = (const float*)d_in[10];
    float* out = (float*)d_out;

    cudaFuncSetAttribute(gemm_att_kernel, cudaFuncAttributeMaxDynamicSharedMemorySize, SMEM_BYTES);
    cudaFuncSetAttribute(gemm_ln_kernel,  cudaFuncAttributeMaxDynamicSharedMemorySize, SMEM_BYTES);

    // Zero degree counters + lookback state via memset nodes (not kernels).
    void* deg_ptr = nullptr;
    void* look_ptr = nullptr;
    cudaGetSymbolAddress(&deg_ptr, d_deg);
    cudaGetSymbolAddress(&look_ptr, d_look);
    cudaMemsetAsync(deg_ptr, 0, 4 * N_NODES * sizeof(int), 0);
    cudaMemsetAsync(look_ptr, 0, 2 * N_TILES * sizeof(unsigned long long), 0);

    degrees_kernel<<<(E_EDGES + 255) / 256, 256>>>(src1, dst1, src2, dst2);
    scan_norm_kernel<<<2 * N_TILES, 256>>>();
    scatter_convert_kernel<<<SCAT_BLOCKS + CONV_BLOCKS + WCONV_BLOCKS, 256>>>(
        src1, dst1, src2, dst2, feat, W1, W2);

    gemm_att_kernel<<<(N_NODES + 63) / 64, 256, SMEM_BYTES>>>(b1);
    gemm_ln_kernel<<<(N_NODES + 63) / 64, 256, SMEM_BYTES>>>(b2, gamma, beta, out);
}

// round 14
// speedup vs baseline: 1.0893x; 1.0893x over previous
#include <cuda_runtime.h>
#include <cuda_fp16.h>
#include <mma.h>
#include <math.h>

using namespace nvcuda;

#define N_NODES 50000
#define E_EDGES 800000
#define DIM 128
#define NHEAD 8
#define HDIM 16
#define LN_EPS 1e-5f
#define FULLMASK 0xFFFFFFFFu
#define N_TILES 196                 // tiles of 256 nodes per graph (scan)
#define TILE 32                     // gemm tile rows

// Scratch (static __device__ arrays: allocation-free per harness rules)
__device__ __half2 d_xh[N_NODES * 64];    // fp16 gather input, pass 1 (feat*norm_src1)
__device__ __half2 d_xh2[N_NODES * 64];   // fp16 gather input, pass 2 (attended*norm_src2)
__device__ int    d_deg[4 * N_NODES];     // [src1 | dst1 | src2 | dst2] degrees
__device__ float  d_norm[4 * N_NODES];    // rsqrt norms, same layout
__device__ int    d_off[2 * N_NODES];     // CSR row offsets [dst1 | dst2]
__device__ int    d_csr[2 * E_EDGES];     // CSR column (source-node) ids [g1 | g2]
__device__ unsigned short d_rank[2 * E_EDGES];  // edge rank within its dst row
__device__ unsigned long long d_look[2 * N_TILES];  // lookback: status(hi32)|value(lo32)
__device__ __half d_wh[2 * DIM * DIM];    // fp16 W1 | W2

// ---------------------------------------------------------------------------
// Zero degrees + lookback state, and convert W1/W2 to fp16 (independent work).
// ---------------------------------------------------------------------------
__global__ void __launch_bounds__(256) zero_w_kernel(const float* __restrict__ W1,
                                                     const float* __restrict__ W2) {
    int i = blockIdx.x * 256 + threadIdx.x;
    if (i < 4 * N_NODES) d_deg[i] = 0;
    if (i < 2 * N_TILES) d_look[i] = 0ULL;
    if (i < 2 * DIM * DIM / 4) {             // 8192 float4s
        const float* W = (i < 4096) ? W1 : W2;
        int li = (i < 4096) ? i : i - 4096;
        float4 v = ((const float4*)W)[li];
        __half2 h0 = __floats2half2_rn(v.x, v.y);
        __half2 h1 = __floats2half2_rn(v.z, v.w);
        uint2 st; st.x = *(unsigned*)&h0; st.y = *(unsigned*)&h1;
        *(uint2*)(d_wh + i * 4) = st;
    }
}

// ---------------------------------------------------------------------------
// Degrees + per-edge dst ranks (atomic return = CSR rank; scatter is atomic-free).
// ---------------------------------------------------------------------------
__global__ void degrees_kernel(const int* __restrict__ s1, const int* __restrict__ t1,
                               const int* __restrict__ s2, const int* __restrict__ t2) {
    int i = blockIdx.x * blockDim.x + threadIdx.x;
    if (i >= E_EDGES) return;
    atomicAdd(&d_deg[0 * N_NODES + s1[i]], 1);
    atomicAdd(&d_deg[2 * N_NODES + s2[i]], 1);
    int p1 = atomicAdd(&d_deg[1 * N_NODES + t1[i]], 1);
    int p2 = atomicAdd(&d_deg[3 * N_NODES + t2[i]], 1);
    d_rank[i] = (unsigned short)p1;
    d_rank[E_EDGES + i] = (unsigned short)p2;
}

// ---------------------------------------------------------------------------
// Fused norms + CSR offsets via decoupled lookback. grid = 2*N_TILES (392) x 256.
// ---------------------------------------------------------------------------
__global__ void __launch_bounds__(256) scan_norm_kernel() {
    __shared__ int ws[8];
    __shared__ int sprefix;
    int bid = blockIdx.x;
    int g = bid / N_TILES, b = bid % N_TILES;
    int t = threadIdx.x, lane = t & 31, w = t >> 5;

    for (int i = bid * 256 + t; i < 4 * N_NODES; i += 2 * N_TILES * 256) {
        int d = d_deg[i];
        d_norm[i] = (d > 0) ? rsqrtf((float)d) : 0.f;
    }

    int degoff = (g ? 3 : 1) * N_NODES;
    int n = b * 256 + t;
    int v = (n < N_NODES) ? d_deg[degoff + n] : 0;
    int x = v;
#pragma unroll
    for (int o = 1; o < 32; o <<= 1) {
        int y = __shfl_up_sync(FULLMASK, x, o);
        if (lane >= o) x += y;
    }
    if (lane == 31) ws[w] = x;
    __syncthreads();
    if (t < 8) {
        int s = ws[t];
#pragma unroll
        for (int o = 1; o < 8; o <<= 1) {
            int y = __shfl_up_sync(0xFFu, s, o);
            if (t >= o) s += y;
        }
        ws[t] = s;
    }
    __syncthreads();
    int incl = x + ((w > 0) ? ws[w - 1] : 0);
    int total = ws[7];

    if (w == 0) {
        if (lane == 0) {
            unsigned long long agg = (1ULL << 32) | (unsigned)total;
            __threadfence();
            atomicExch(&d_look[bid], agg);
        }
        __syncwarp();
        int running = 0;
        if (b == 0) {
            if (lane == 0) {
                unsigned long long inc = (2ULL << 32) | (unsigned)total;
                __threadfence();
                atomicExch(&d_look[bid], inc);
                sprefix = 0;
            }
        } else {
            int jend = b - 1;
            bool done = false;
            while (!done) {
                int j = jend - lane;
                unsigned long long e = (j >= 0)
                    ? atomicAdd(&d_look[g * N_TILES + j], 0ULL)
                    : (2ULL << 32);
                unsigned st = (unsigned)(e >> 32);
                if (__ballot_sync(FULLMASK, st == 0)) continue;
                unsigned ball2 = __ballot_sync(FULLMASK, (st == 2) && (j >= 0));
                int firstlane = ball2 ? (__ffs(ball2) - 1) : 32;
                int val = ((lane <= firstlane) && (j >= 0)) ? (int)(unsigned)e : 0;
#pragma unroll
                for (int o = 16; o > 0; o >>= 1) val += __shfl_down_sync(FULLMASK, val, o);
                if (lane == 0) running += val;
                if (firstlane < 32) done = true;
                else { jend -= 32; if (jend < 0) done = true; }
            }
            if (lane == 0) {
                unsigned long long inc = (2ULL << 32) | (unsigned)(running + total);
                __threadfence();
                atomicExch(&d_look[bid], inc);
                sprefix = running;
            }
        }
    }
    __syncthreads();
    if (n < N_NODES) {
        d_off[g * N_NODES + n] = sprefix + incl - v;   // exclusive
    }
}

// ---------------------------------------------------------------------------
// Atomic-free CSR scatter + feature fp16 convert.
// ---------------------------------------------------------------------------
#define SCAT_BLOCKS ((2 * E_EDGES) / 256)        // 6250
#define CONV_BLOCKS ((N_NODES * 32 + 255) / 256) // 6250
__global__ void scatter_convert_kernel(const int* __restrict__ s1, const int* __restrict__ t1,
                                       const int* __restrict__ s2, const int* __restrict__ t2,
                                       const float* __restrict__ feat) {
    int bid = blockIdx.x;
    if (bid < SCAT_BLOCKS) {
        int i = bid * 256 + threadIdx.x;
        if (i < E_EDGES) {
            int p = d_off[0 * N_NODES + t1[i]] + (int)d_rank[i];
            d_csr[p] = s1[i];
        } else {
            int e = i - E_EDGES;
            int p = d_off[1 * N_NODES + t2[e]] + (int)d_rank[E_EDGES + e];
            d_csr[E_EDGES + p] = s2[e];
        }
    } else {
        int i = (bid - SCAT_BLOCKS) * 256 + threadIdx.x;
        if (i >= N_NODES * 32) return;
        int n = i >> 5, c4 = i & 31;
        float nm = d_norm[n];                       // src1 norms at offset 0
        float4 v = ((const float4*)feat)[i];
        __half2 h0 = __floats2half2_rn(v.x * nm, v.y * nm);
        __half2 h1 = __floats2half2_rn(v.z * nm, v.w * nm);
        uint2 st; st.x = *(unsigned*)&h0; st.y = *(unsigned*)&h1;
        *(uint2*)(d_xh + n * 64 + c4 * 2) = st;
    }
}

// ---------------------------------------------------------------------------
// Fused gather + tensor-core GEMM. 32-row tiles, 5 blocks/SM.
// smem layout (bytes):
//   [0, 34816)       Ws_h: half[128][136]  -- later aliased by C (fp32 32x132)
//   [34816, 43520)   As_h: half[32][136]
//   [43520, 45568)   red:  float[512]
// ---------------------------------------------------------------------------
#define WS_H_OFF 0
#define AS_H_OFF 34816
#define RED_OFF  43520
#define SMEM_BYTES 45568
#define A_LDH 136
#define C_LDF 132

__device__ __forceinline__ void acc_half16(float4& a0, float4& a1, uint4 r) {
    __half2 h0 = *(__half2*)&r.x;
    __half2 h1 = *(__half2*)&r.y;
    __half2 h2 = *(__half2*)&r.z;
    __half2 h3 = *(__half2*)&r.w;
    float2 f0 = __half22float2(h0);
    float2 f1 = __half22float2(h1);
    float2 f2 = __half22float2(h2);
    float2 f3 = __half22float2(h3);
    a0.x += f0.x; a0.y += f0.y; a0.z += f1.x; a0.w += f1.y;
    a1.x += f2.x; a1.y += f2.y; a1.z += f3.x; a1.w += f3.y;
}

// fp16 pairwise pre-add (depth 1), then fp32 accumulate.
__device__ __forceinline__ void acc_pair(float4& a0, float4& a1, uint4 rA, uint4 rB) {
    __half2 s0 = __hadd2(*(__half2*)&rA.x, *(__half2*)&rB.x);
    __half2 s1 = __hadd2(*(__half2*)&rA.y, *(__half2*)&rB.y);
    __half2 s2 = __hadd2(*(__half2*)&rA.z, *(__half2*)&rB.z);
    __half2 s3 = __hadd2(*(__half2*)&rA.w, *(__half2*)&rB.w);
    float2 f0 = __half22float2(s0);
    float2 f1 = __half22float2(s1);
    float2 f2 = __half22float2(s2);
    float2 f3 = __half22float2(s3);
    a0.x += f0.x; a0.y += f0.y; a0.z += f1.x; a0.w += f1.y;
    a1.x += f2.x; a1.y += f2.y; a1.z += f3.x; a1.w += f3.y;
}

__device__ __forceinline__ void gather_gemm_mainloop(char* smem, int graph, int w_off,
                                                     const __half2* __restrict__ base,
                                                     const float* __restrict__ bias,
                                                     int norm_off, int m0) {
    __half* Ws = (__half*)(smem + WS_H_OFF);
    __half* As = (__half*)(smem + AS_H_OFF);
    float*  C  = (float*)smem;
    int tid = threadIdx.x;

    // --- Phase 1: W fp16 (128x128) -> smem ld=136 (uint4 copies) ---
    const __half* Wh = d_wh + w_off;
#pragma unroll
    for (int j = 0; j < 8; j++) {
        int idx = j * 256 + tid;            // uint4 index, 2048 total
        int row = idx >> 4, c8 = idx & 15;  // 16 uint4 per row (128 halves)
        uint4 v = ((const uint4*)Wh)[idx];
        *(uint4*)(Ws + row * A_LDH + c8 * 8) = v;
    }

    // --- Phase 2: CSR gather directly into fp16 A smem ---
    int hw = tid >> 4;                       // half-warp 0..15
    int lane16 = tid & 15;
    unsigned hmask = 0xFFFFu << (tid & 16);
    int degseg = (graph == 0 ? 1 : 3) * N_NODES;
    const int* csr = d_csr + graph * E_EDGES;

#pragma unroll
    for (int k = 0; k < 2; k++) {            // 2 rows per half-warp (32-row tile)
        int n_local = k * 16 + hw;
        int gnode = m0 + n_local;
        float4 a00 = make_float4(0.f,0.f,0.f,0.f), a01 = make_float4(0.f,0.f,0.f,0.f);
        float4 a10 = make_float4(0.f,0.f,0.f,0.f), a11 = make_float4(0.f,0.f,0.f,0.f);
        float nm = 0.f;
        if (gnode < N_NODES) {
            nm = d_norm[norm_off + gnode];
            int beg = d_off[graph * N_NODES + gnode];
            int cnt = d_deg[degseg + gnode];
            for (int j0 = 0; j0 < cnt; j0 += 16) {
                int m = min(16, cnt - j0);
                int s_l = (lane16 < m) ? csr[beg + j0 + lane16] : 0;
                int jj = 0;
                for (; jj + 3 < m; jj += 4) {
                    int sA = __shfl_sync(hmask, s_l, jj,     16);
                    int sB = __shfl_sync(hmask, s_l, jj + 1, 16);
                    int sC = __shfl_sync(hmask, s_l, jj + 2, 16);
                    int sD = __shfl_sync(hmask, s_l, jj + 3, 16);
                    uint4 rA = *(const uint4*)(base + sA * 64 + lane16 * 4);
                    uint4 rB = *(const uint4*)(base + sB * 64 + lane16 * 4);
                    uint4 rC = *(const uint4*)(base + sC * 64 + lane16 * 4);
                    uint4 rD = *(const uint4*)(base + sD * 64 + lane16 * 4);
                    acc_pair(a00, a01, rA, rB);     // fp16 pre-add, fp32 accumulate
                    acc_pair(a10, a11, rC, rD);
                }
                for (; jj < m; jj++) {
                    int sA = __shfl_sync(hmask, s_l, jj, 16);
                    uint4 rA = *(const uint4*)(base + sA * 64 + lane16 * 4);
                    acc_half16(a00, a01, rA);
                }
            }
        }
        a00.x += a10.x; a00.y += a10.y; a00.z += a10.z; a00.w += a10.w;
        a01.x += a11.x; a01.y += a11.y; a01.z += a11.z; a01.w += a11.w;
        __half2 h0 = __floats2half2_rn(a00.x * nm, a00.y * nm);
        __half2 h1 = __floats2half2_rn(a00.z * nm, a00.w * nm);
        __half2 h2 = __floats2half2_rn(a01.x * nm, a01.y * nm);
        __half2 h3 = __floats2half2_rn(a01.z * nm, a01.w * nm);
        uint4 st;
        st.x = *(unsigned int*)&h0;
        st.y = *(unsigned int*)&h1;
        st.z = *(unsigned int*)&h2;
        st.w = *(unsigned int*)&h3;
        *(uint4*)(As + n_local * A_LDH + lane16 * 8) = st;
    }
    __syncthreads();

    // --- Phase 3: wmma mainloop (8 warps: 2 row-groups x 4 col-groups) ---
    int wid = tid >> 5;
    int wm = wid & 1;        // 2 row-groups of 16
    int wn = wid >> 1;       // 4 col-groups of 32

    wmma::fragment<wmma::accumulator, 16, 16, 16, float> acc[2];
#pragma unroll
    for (int n = 0; n < 2; n++) wmma::fill_fragment(acc[n], 0.f);

#pragma unroll
    for (int k = 0; k < 8; k++) {
        wmma::fragment<wmma::matrix_a, 16, 16, 16, __half, wmma::row_major> fa;
        wmma::load_matrix_sync(fa, As + (wm * 16) * A_LDH + k * 16, A_LDH);
#pragma unroll
        for (int n = 0; n < 2; n++) {
            wmma::fragment<wmma::matrix_b, 16, 16, 16, __half, wmma::row_major> fb;
            wmma::load_matrix_sync(fb, Ws + (k * 16) * A_LDH + wn * 32 + n * 16, A_LDH);
            wmma::mma_sync(acc[n], fa, fb, acc[n]);
        }
    }
    __syncthreads();   // done reading Ws/As; C aliases Ws region

#pragma unroll
    for (int n = 0; n < 2; n++)
        wmma::store_matrix_sync(C + (wm * 16) * C_LDF + wn * 32 + n * 16,
                                acc[n], C_LDF, wmma::mem_row_major);
    __syncthreads();

    // bias + ReLU in place (32x128 = 1024 float4)
#pragma unroll
    for (int j = 0; j < 4; j++) {
        int idx = j * 256 + tid;
        int r = idx >> 5, c4 = idx & 31;
        float4 v = *(float4*)(C + r * C_LDF + c4 * 4);
        float4 bv = ((const float4*)bias)[c4];
        v.x = fmaxf(v.x + bv.x, 0.f);
        v.y = fmaxf(v.y + bv.y, 0.f);
        v.z = fmaxf(v.z + bv.z, 0.f);
        v.w = fmaxf(v.w + bv.w, 0.f);
        *(float4*)(C + r * C_LDF + c4 * 4) = v;
    }
    __syncthreads();
}

// gather(g1, from d_xh) + GEMM1 + attention + src2-norm prescale -> d_xh2 (fp16)
__global__ void __launch_bounds__(256, 5)
gemm_att_kernel(const float* __restrict__ bias) {
    extern __shared__ char smc[];
    float* As  = (float*)smc;                 // C tile (32 x 132)
    float* red = (float*)(smc + RED_OFF);
    int tid = threadIdx.x;
    int m0 = blockIdx.x * TILE;

    gather_gemm_mainloop(smc, 0, 0, d_xh, bias, 1 * N_NODES, m0);

    // scores: row = tid>>3 (0..31), head = tid&7
    {
        int row = tid >> 3, h = tid & 7;
        float s = 0.f;
#pragma unroll
        for (int c = 0; c < HDIM; c++) {
            float v = As[row * C_LDF + h * HDIM + c];
            s += v * v;
        }
        red[row * 8 + h] = s * 0.25f;          // / sqrt(HD)=4
    }
    __syncthreads();
    if ((tid & 7) == 0) {
        int row = tid >> 3;
        float sc[8], mx = -1e30f;
#pragma unroll
        for (int h = 0; h < 8; h++) { sc[h] = red[row * 8 + h]; mx = fmaxf(mx, sc[h]); }
        float sum = 0.f;
#pragma unroll
        for (int h = 0; h < 8; h++) { sc[h] = expf(sc[h] - mx); sum += sc[h]; }
        float inv = 1.f / sum;
#pragma unroll
        for (int h = 0; h < 8; h++) red[row * 8 + h] = sc[h] * inv;
    }
    __syncthreads();
    {
        int row = tid >> 3, q = tid & 7;       // q owns head q's 16 cols
        int g = m0 + row;
        if (g < N_NODES) {
            float p = red[row * 8 + q] * d_norm[2 * N_NODES + g];
#pragma unroll
            for (int j = 0; j < 4; j++) {
                int col = q * 16 + j * 4;
                float4 v = *(float4*)(As + row * C_LDF + col);
                __half2 h0 = __floats2half2_rn(v.x * p, v.y * p);
                __half2 h1 = __floats2half2_rn(v.z * p, v.w * p);
                uint2 st;
                st.x = *(unsigned int*)&h0;
                st.y = *(unsigned int*)&h1;
                *(uint2*)(d_xh2 + g * 64 + (col >> 1)) = st;   // double buffer
            }
        }
    }
}

// gather(g2, from d_xh2) + GEMM2 + LayerNorm -> out
__global__ void __launch_bounds__(256, 5)
gemm_ln_kernel(const float* __restrict__ bias,
               const float* __restrict__ gamma, const float* __restrict__ beta,
               float* __restrict__ out) {
    extern __shared__ char smc[];
    float* As  = (float*)smc;                 // C tile (32 x 132)
    float* red = (float*)(smc + RED_OFF);     // [0,256): sums, [256,512): sumsq
    int tid = threadIdx.x;
    int m0 = blockIdx.x * TILE;

    gather_gemm_mainloop(smc, 1, DIM * DIM, d_xh2, bias, 3 * N_NODES, m0);

    {
        int row = tid >> 3, q = tid & 7;
        float s = 0.f, s2 = 0.f;
#pragma unroll
        for (int c = 0; c < 16; c++) {
            float v = As[row * C_LDF + q * 16 + c];
            s += v; s2 += v * v;
        }
        red[tid] = s;
        red[256 + tid] = s2;
    }
    __syncthreads();
    if ((tid & 7) == 0) {
        int row = tid >> 3;
        float s = 0.f, s2 = 0.f;
#pragma unroll
        for (int q = 0; q < 8; q++) { s += red[row * 8 + q]; s2 += red[256 + row * 8 + q]; }
        float mu = s * (1.f / 128.f);
        float var = s2 * (1.f / 128.f) - mu * mu;
        red[row * 8 + 0] = mu;
        red[row * 8 + 1] = rsqrtf(var + LN_EPS);
    }
    __syncthreads();
    {
        int row = tid >> 3, q = tid & 7;
        int g = m0 + row;
        if (g < N_NODES) {
            float mu = red[row * 8 + 0];
            float rstd = red[row * 8 + 1];
#pragma unroll
            for (int j = 0; j < 4; j++) {
                int col = q * 16 + j * 4;
                float4 v = *(float4*)(As + row * C_LDF + col);
                float4 gm = ((const float4*)gamma)[col >> 2];
                float4 bt = ((const float4*)beta)[col >> 2];
                v.x = (v.x - mu) * rstd * gm.x + bt.x;
                v.y = (v.y - mu) * rstd * gm.y + bt.y;
                v.z = (v.z - mu) * rstd * gm.z + bt.z;
                v.w = (v.w - mu) * rstd * gm.w + bt.w;
                *(float4*)(out + g * DIM + col) = v;
            }
        }
    }
}

// ---------------------------------------------------------------------------
extern "C" void kernel_launch(void* const* d_in, const int* in_sizes, int n_in,
                              void* d_out, int out_size) {
    const float* feat  = (const float*)d_in[0];
    const int*   src1  = (const int*)d_in[1];
    const int*   dst1  = (const int*)d_in[2];
    const int*   src2  = (const int*)d_in[3];
    const int*   dst2  = (const int*)d_in[4];
    const float* W1    = (const float*)d_in[5];
    const float* b1    = (const float*)d_in[6];
    const float* W2    = (const float*)d_in[7];
    const float* b2    = (const float*)d_in[8];
    const float* gamma = (const float*)d_in[9];
    const float* beta  = (const float*)d_in[10];
    float* out = (float*)d_out;

    cudaFuncSetAttribute(gemm_att_kernel, cudaFuncAttributeMaxDynamicSharedMemorySize, SMEM_BYTES);
    cudaFuncSetAttribute(gemm_ln_kernel,  cudaFuncAttributeMaxDynamicSharedMemorySize, SMEM_BYTES);

    zero_w_kernel<<<(4 * N_NODES + 255) / 256, 256>>>(W1, W2);
    degrees_kernel<<<(E_EDGES + 255) / 256, 256>>>(src1, dst1, src2, dst2);
    scan_norm_kernel<<<2 * N_TILES, 256>>>();
    scatter_convert_kernel<<<SCAT_BLOCKS + CONV_BLOCKS, 256>>>(src1, dst1, src2, dst2, feat);

    const int gemm_blocks = (N_NODES + TILE - 1) / TILE;   // 1563
    gemm_att_kernel<<<gemm_blocks, 256, SMEM_BYTES>>>(b1);
    gemm_ln_kernel<<<gemm_blocks, 256, SMEM_BYTES>>>(b2, gamma, beta, out);
}

// round 15
// speedup vs baseline: 1.1182x; 1.0265x over previous
#include <cuda_runtime.h>
#include <cuda_fp16.h>
#include <mma.h>
#include <math.h>

using namespace nvcuda;

#define N_NODES 50000
#define E_EDGES 800000
#define DIM 128
#define NHEAD 8
#define HDIM 16
#define LN_EPS 1e-5f
#define FULLMASK 0xFFFFFFFFu
#define N_TILES 196                 // tiles of 256 nodes per graph (scan)
#define TILE 32                     // gemm tile rows

// Scratch (static __device__ arrays: allocation-free per harness rules)
__device__ __half2 d_xh[N_NODES * 64];    // fp16 gather input, pass 1 (feat*norm_src1)
__device__ __half2 d_xh2[N_NODES * 64];   // fp16 gather input, pass 2 (attended*norm_src2)
__device__ int    d_deg[4 * N_NODES];     // [src1 | dst1 | src2 | dst2] degrees
__device__ float  d_norm[4 * N_NODES];    // rsqrt norms, same layout
__device__ int    d_off[2 * N_NODES];     // CSR row offsets [dst1 | dst2]
__device__ int    d_csr[2 * E_EDGES];     // CSR column (source-node) ids [g1 | g2]
__device__ unsigned short d_rank[2 * E_EDGES];  // edge rank within its dst row
__device__ unsigned long long d_look[2 * N_TILES];  // lookback: status(hi32)|value(lo32)
__device__ __half d_wh[2 * DIM * DIM];    // fp16 W1 | W2

// ---------------------------------------------------------------------------
// Zero degrees + lookback state, and convert W1/W2 to fp16 (independent work).
// ---------------------------------------------------------------------------
__global__ void __launch_bounds__(256) zero_w_kernel(const float* __restrict__ W1,
                                                     const float* __restrict__ W2) {
    int i = blockIdx.x * 256 + threadIdx.x;
    if (i < 4 * N_NODES) d_deg[i] = 0;
    if (i < 2 * N_TILES) d_look[i] = 0ULL;
    if (i < 2 * DIM * DIM / 4) {             // 8192 float4s
        const float* W = (i < 4096) ? W1 : W2;
        int li = (i < 4096) ? i : i - 4096;
        float4 v = ((const float4*)W)[li];
        __half2 h0 = __floats2half2_rn(v.x, v.y);
        __half2 h1 = __floats2half2_rn(v.z, v.w);
        uint2 st; st.x = *(unsigned*)&h0; st.y = *(unsigned*)&h1;
        *(uint2*)(d_wh + i * 4) = st;
    }
}

// ---------------------------------------------------------------------------
// Degrees + per-edge dst ranks (atomic return = CSR rank; scatter is atomic-free).
// ---------------------------------------------------------------------------
__global__ void degrees_kernel(const int* __restrict__ s1, const int* __restrict__ t1,
                               const int* __restrict__ s2, const int* __restrict__ t2) {
    int i = blockIdx.x * blockDim.x + threadIdx.x;
    if (i >= E_EDGES) return;
    atomicAdd(&d_deg[0 * N_NODES + s1[i]], 1);
    atomicAdd(&d_deg[2 * N_NODES + s2[i]], 1);
    int p1 = atomicAdd(&d_deg[1 * N_NODES + t1[i]], 1);
    int p2 = atomicAdd(&d_deg[3 * N_NODES + t2[i]], 1);
    d_rank[i] = (unsigned short)p1;
    d_rank[E_EDGES + i] = (unsigned short)p2;
}

// ---------------------------------------------------------------------------
// Fused norms + CSR offsets via decoupled lookback. grid = 2*N_TILES (392) x 256.
// ---------------------------------------------------------------------------
__global__ void __launch_bounds__(256) scan_norm_kernel() {
    __shared__ int ws[8];
    __shared__ int sprefix;
    int bid = blockIdx.x;
    int g = bid / N_TILES, b = bid % N_TILES;
    int t = threadIdx.x, lane = t & 31, w = t >> 5;

    for (int i = bid * 256 + t; i < 4 * N_NODES; i += 2 * N_TILES * 256) {
        int d = d_deg[i];
        d_norm[i] = (d > 0) ? rsqrtf((float)d) : 0.f;
    }

    int degoff = (g ? 3 : 1) * N_NODES;
    int n = b * 256 + t;
    int v = (n < N_NODES) ? d_deg[degoff + n] : 0;
    int x = v;
#pragma unroll
    for (int o = 1; o < 32; o <<= 1) {
        int y = __shfl_up_sync(FULLMASK, x, o);
        if (lane >= o) x += y;
    }
    if (lane == 31) ws[w] = x;
    __syncthreads();
    if (t < 8) {
        int s = ws[t];
#pragma unroll
        for (int o = 1; o < 8; o <<= 1) {
            int y = __shfl_up_sync(0xFFu, s, o);
            if (t >= o) s += y;
        }
        ws[t] = s;
    }
    __syncthreads();
    int incl = x + ((w > 0) ? ws[w - 1] : 0);
    int total = ws[7];

    if (w == 0) {
        if (lane == 0) {
            unsigned long long agg = (1ULL << 32) | (unsigned)total;
            __threadfence();
            atomicExch(&d_look[bid], agg);
        }
        __syncwarp();
        int running = 0;
        if (b == 0) {
            if (lane == 0) {
                unsigned long long inc = (2ULL << 32) | (unsigned)total;
                __threadfence();
                atomicExch(&d_look[bid], inc);
                sprefix = 0;
            }
        } else {
            int jend = b - 1;
            bool done = false;
            while (!done) {
                int j = jend - lane;
                unsigned long long e = (j >= 0)
                    ? atomicAdd(&d_look[g * N_TILES + j], 0ULL)
                    : (2ULL << 32);
                unsigned st = (unsigned)(e >> 32);
                if (__ballot_sync(FULLMASK, st == 0)) continue;
                unsigned ball2 = __ballot_sync(FULLMASK, (st == 2) && (j >= 0));
                int firstlane = ball2 ? (__ffs(ball2) - 1) : 32;
                int val = ((lane <= firstlane) && (j >= 0)) ? (int)(unsigned)e : 0;
#pragma unroll
                for (int o = 16; o > 0; o >>= 1) val += __shfl_down_sync(FULLMASK, val, o);
                if (lane == 0) running += val;
                if (firstlane < 32) done = true;
                else { jend -= 32; if (jend < 0) done = true; }
            }
            if (lane == 0) {
                unsigned long long inc = (2ULL << 32) | (unsigned)(running + total);
                __threadfence();
                atomicExch(&d_look[bid], inc);
                sprefix = running;
            }
        }
    }
    __syncthreads();
    if (n < N_NODES) {
        d_off[g * N_NODES + n] = sprefix + incl - v;   // exclusive
    }
}

// ---------------------------------------------------------------------------
// Atomic-free CSR scatter + feature fp16 convert.
// ---------------------------------------------------------------------------
#define SCAT_BLOCKS ((2 * E_EDGES) / 256)        // 6250
#define CONV_BLOCKS ((N_NODES * 32 + 255) / 256) // 6250
__global__ void scatter_convert_kernel(const int* __restrict__ s1, const int* __restrict__ t1,
                                       const int* __restrict__ s2, const int* __restrict__ t2,
                                       const float* __restrict__ feat) {
    int bid = blockIdx.x;
    if (bid < SCAT_BLOCKS) {
        int i = bid * 256 + threadIdx.x;
        if (i < E_EDGES) {
            int p = d_off[0 * N_NODES + t1[i]] + (int)d_rank[i];
            d_csr[p] = s1[i];
        } else {
            int e = i - E_EDGES;
            int p = d_off[1 * N_NODES + t2[e]] + (int)d_rank[E_EDGES + e];
            d_csr[E_EDGES + p] = s2[e];
        }
    } else {
        int i = (bid - SCAT_BLOCKS) * 256 + threadIdx.x;
        if (i >= N_NODES * 32) return;
        int n = i >> 5, c4 = i & 31;
        float nm = d_norm[n];                       // src1 norms at offset 0
        float4 v = ((const float4*)feat)[i];
        __half2 h0 = __floats2half2_rn(v.x * nm, v.y * nm);
        __half2 h1 = __floats2half2_rn(v.z * nm, v.w * nm);
        uint2 st; st.x = *(unsigned*)&h0; st.y = *(unsigned*)&h1;
        *(uint2*)(d_xh + n * 64 + c4 * 2) = st;
    }
}

// ---------------------------------------------------------------------------
// Fused gather + tensor-core GEMM. 32-row tiles, 5 blocks/SM.
// smem layout (bytes):
//   [0, 34816)       Ws_h: half[128][136]  -- later aliased by C (fp32 32x132)
//   [34816, 43520)   As_h: half[32][136]
//   [43520, 45568)   red:  float[512]
// ---------------------------------------------------------------------------
#define WS_H_OFF 0
#define AS_H_OFF 34816
#define RED_OFF  43520
#define SMEM_BYTES 45568
#define A_LDH 136
#define C_LDF 132

__device__ __forceinline__ void acc_half16(float4& a0, float4& a1, uint4 r) {
    __half2 h0 = *(__half2*)&r.x;
    __half2 h1 = *(__half2*)&r.y;
    __half2 h2 = *(__half2*)&r.z;
    __half2 h3 = *(__half2*)&r.w;
    float2 f0 = __half22float2(h0);
    float2 f1 = __half22float2(h1);
    float2 f2 = __half22float2(h2);
    float2 f3 = __half22float2(h3);
    a0.x += f0.x; a0.y += f0.y; a0.z += f1.x; a0.w += f1.y;
    a1.x += f2.x; a1.y += f2.y; a1.z += f3.x; a1.w += f3.y;
}

// fp16 depth-2 tree pre-add of 4 edges: (A+B)+(C+D), then fp32 accumulate.
__device__ __forceinline__ void acc_quad(float4& a0, float4& a1,
                                         uint4 rA, uint4 rB, uint4 rC, uint4 rD) {
    __half2 s0 = __hadd2(__hadd2(*(__half2*)&rA.x, *(__half2*)&rB.x),
                         __hadd2(*(__half2*)&rC.x, *(__half2*)&rD.x));
    __half2 s1 = __hadd2(__hadd2(*(__half2*)&rA.y, *(__half2*)&rB.y),
                         __hadd2(*(__half2*)&rC.y, *(__half2*)&rD.y));
    __half2 s2 = __hadd2(__hadd2(*(__half2*)&rA.z, *(__half2*)&rB.z),
                         __hadd2(*(__half2*)&rC.z, *(__half2*)&rD.z));
    __half2 s3 = __hadd2(__hadd2(*(__half2*)&rA.w, *(__half2*)&rB.w),
                         __hadd2(*(__half2*)&rC.w, *(__half2*)&rD.w));
    float2 f0 = __half22float2(s0);
    float2 f1 = __half22float2(s1);
    float2 f2 = __half22float2(s2);
    float2 f3 = __half22float2(s3);
    a0.x += f0.x; a0.y += f0.y; a0.z += f1.x; a0.w += f1.y;
    a1.x += f2.x; a1.y += f2.y; a1.z += f3.x; a1.w += f3.y;
}

__device__ __forceinline__ void gather_gemm_mainloop(char* smem, int graph, int w_off,
                                                     const __half2* __restrict__ base,
                                                     const float* __restrict__ bias,
                                                     int norm_off, int m0) {
    __half* Ws = (__half*)(smem + WS_H_OFF);
    __half* As = (__half*)(smem + AS_H_OFF);
    float*  C  = (float*)smem;
    int tid = threadIdx.x;

    // --- Phase 1: W fp16 (128x128) -> smem ld=136 (uint4 copies) ---
    const __half* Wh = d_wh + w_off;
#pragma unroll
    for (int j = 0; j < 8; j++) {
        int idx = j * 256 + tid;            // uint4 index, 2048 total
        int row = idx >> 4, c8 = idx & 15;  // 16 uint4 per row (128 halves)
        uint4 v = ((const uint4*)Wh)[idx];
        *(uint4*)(Ws + row * A_LDH + c8 * 8) = v;
    }

    // --- Phase 2: CSR gather directly into fp16 A smem ---
    int hw = tid >> 4;                       // half-warp 0..15
    int lane16 = tid & 15;
    unsigned hmask = 0xFFFFu << (tid & 16);
    int degseg = (graph == 0 ? 1 : 3) * N_NODES;
    const int* csr = d_csr + graph * E_EDGES;

#pragma unroll
    for (int k = 0; k < 2; k++) {            // 2 rows per half-warp (32-row tile)
        int n_local = k * 16 + hw;
        int gnode = m0 + n_local;
        float4 a00 = make_float4(0.f,0.f,0.f,0.f), a01 = make_float4(0.f,0.f,0.f,0.f);
        float nm = 0.f;
        if (gnode < N_NODES) {
            nm = d_norm[norm_off + gnode];
            int beg = d_off[graph * N_NODES + gnode];
            int cnt = d_deg[degseg + gnode];
            for (int j0 = 0; j0 < cnt; j0 += 16) {
                int m = min(16, cnt - j0);
                int s_l = (lane16 < m) ? csr[beg + j0 + lane16] : 0;
                int jj = 0;
                for (; jj + 3 < m; jj += 4) {
                    int sA = __shfl_sync(hmask, s_l, jj,     16);
                    int sB = __shfl_sync(hmask, s_l, jj + 1, 16);
                    int sC = __shfl_sync(hmask, s_l, jj + 2, 16);
                    int sD = __shfl_sync(hmask, s_l, jj + 3, 16);
                    uint4 rA = *(const uint4*)(base + sA * 64 + lane16 * 4);
                    uint4 rB = *(const uint4*)(base + sB * 64 + lane16 * 4);
                    uint4 rC = *(const uint4*)(base + sC * 64 + lane16 * 4);
                    uint4 rD = *(const uint4*)(base + sD * 64 + lane16 * 4);
                    acc_quad(a00, a01, rA, rB, rC, rD);   // fp16 depth-2 tree pre-add
                }
                for (; jj < m; jj++) {
                    int sA = __shfl_sync(hmask, s_l, jj, 16);
                    uint4 rA = *(const uint4*)(base + sA * 64 + lane16 * 4);
                    acc_half16(a00, a01, rA);
                }
            }
        }
        __half2 h0 = __floats2half2_rn(a00.x * nm, a00.y * nm);
        __half2 h1 = __floats2half2_rn(a00.z * nm, a00.w * nm);
        __half2 h2 = __floats2half2_rn(a01.x * nm, a01.y * nm);
        __half2 h3 = __floats2half2_rn(a01.z * nm, a01.w * nm);
        uint4 st;
        st.x = *(unsigned int*)&h0;
        st.y = *(unsigned int*)&h1;
        st.z = *(unsigned int*)&h2;
        st.w = *(unsigned int*)&h3;
        *(uint4*)(As + n_local * A_LDH + lane16 * 8) = st;
    }
    __syncthreads();

    // --- Phase 3: wmma mainloop (8 warps: 2 row-groups x 4 col-groups) ---
    int wid = tid >> 5;
    int wm = wid & 1;        // 2 row-groups of 16
    int wn = wid >> 1;       // 4 col-groups of 32

    wmma::fragment<wmma::accumulator, 16, 16, 16, float> acc[2];
#pragma unroll
    for (int n = 0; n < 2; n++) wmma::fill_fragment(acc[n], 0.f);

#pragma unroll
    for (int k = 0; k < 8; k++) {
        wmma::fragment<wmma::matrix_a, 16, 16, 16, __half, wmma::row_major> fa;
        wmma::load_matrix_sync(fa, As + (wm * 16) * A_LDH + k * 16, A_LDH);
#pragma unroll
        for (int n = 0; n < 2; n++) {
            wmma::fragment<wmma::matrix_b, 16, 16, 16, __half, wmma::row_major> fb;
            wmma::load_matrix_sync(fb, Ws + (k * 16) * A_LDH + wn * 32 + n * 16, A_LDH);
            wmma::mma_sync(acc[n], fa, fb, acc[n]);
        }
    }
    __syncthreads();   // done reading Ws/As; C aliases Ws region

#pragma unroll
    for (int n = 0; n < 2; n++)
        wmma::store_matrix_sync(C + (wm * 16) * C_LDF + wn * 32 + n * 16,
                                acc[n], C_LDF, wmma::mem_row_major);
    __syncthreads();

    // bias + ReLU in place (32x128 = 1024 float4)
#pragma unroll
    for (int j = 0; j < 4; j++) {
        int idx = j * 256 + tid;
        int r = idx >> 5, c4 = idx & 31;
        float4 v = *(float4*)(C + r * C_LDF + c4 * 4);
        float4 bv = ((const float4*)bias)[c4];
        v.x = fmaxf(v.x + bv.x, 0.f);
        v.y = fmaxf(v.y + bv.y, 0.f);
        v.z = fmaxf(v.z + bv.z, 0.f);
        v.w = fmaxf(v.w + bv.w, 0.f);
        *(float4*)(C + r * C_LDF + c4 * 4) = v;
    }
    __syncthreads();
}

// gather(g1, from d_xh) + GEMM1 + attention + src2-norm prescale -> d_xh2 (fp16)
__global__ void __launch_bounds__(256, 5)
gemm_att_kernel(const float* __restrict__ bias) {
    extern __shared__ char smc[];
    float* As  = (float*)smc;                 // C tile (32 x 132)
    float* red = (float*)(smc + RED_OFF);
    int tid = threadIdx.x;
    int m0 = blockIdx.x * TILE;

    gather_gemm_mainloop(smc, 0, 0, d_xh, bias, 1 * N_NODES, m0);

    // scores: row = tid>>3 (0..31), head = tid&7
    {
        int row = tid >> 3, h = tid & 7;
        float s = 0.f;
#pragma unroll
        for (int c = 0; c < HDIM; c++) {
            float v = As[row * C_LDF + h * HDIM + c];
            s += v * v;
        }
        red[row * 8 + h] = s * 0.25f;          // / sqrt(HD)=4
    }
    __syncthreads();
    if ((tid & 7) == 0) {
        int row = tid >> 3;
        float sc[8], mx = -1e30f;
#pragma unroll
        for (int h = 0; h < 8; h++) { sc[h] = red[row * 8 + h]; mx = fmaxf(mx, sc[h]); }
        float sum = 0.f;
#pragma unroll
        for (int h = 0; h < 8; h++) { sc[h] = expf(sc[h] - mx); sum += sc[h]; }
        float inv = 1.f / sum;
#pragma unroll
        for (int h = 0; h < 8; h++) red[row * 8 + h] = sc[h] * inv;
    }
    __syncthreads();
    {
        int row = tid >> 3, q = tid & 7;       // q owns head q's 16 cols
        int g = m0 + row;
        if (g < N_NODES) {
            float p = red[row * 8 + q] * d_norm[2 * N_NODES + g];
#pragma unroll
            for (int j = 0; j < 4; j++) {
                int col = q * 16 + j * 4;
                float4 v = *(float4*)(As + row * C_LDF + col);
                __half2 h0 = __floats2half2_rn(v.x * p, v.y * p);
                __half2 h1 = __floats2half2_rn(v.z * p, v.w * p);
                uint2 st;
                st.x = *(unsigned int*)&h0;
                st.y = *(unsigned int*)&h1;
                *(uint2*)(d_xh2 + g * 64 + (col >> 1)) = st;   // double buffer
            }
        }
    }
}

// gather(g2, from d_xh2) + GEMM2 + LayerNorm -> out
__global__ void __launch_bounds__(256, 5)
gemm_ln_kernel(const float* __restrict__ bias,
               const float* __restrict__ gamma, const float* __restrict__ beta,
               float* __restrict__ out) {
    extern __shared__ char smc[];
    float* As  = (float*)smc;                 // C tile (32 x 132)
    float* red = (float*)(smc + RED_OFF);     // [0,256): sums, [256,512): sumsq
    int tid = threadIdx.x;
    int m0 = blockIdx.x * TILE;

    gather_gemm_mainloop(smc, 1, DIM * DIM, d_xh2, bias, 3 * N_NODES, m0);

    {
        int row = tid >> 3, q = tid & 7;
        float s = 0.f, s2 = 0.f;
#pragma unroll
        for (int c = 0; c < 16; c++) {
            float v = As[row * C_LDF + q * 16 + c];
            s += v; s2 += v * v;
        }
        red[tid] = s;
        red[256 + tid] = s2;
    }
    __syncthreads();
    if ((tid & 7) == 0) {
        int row = tid >> 3;
        float s = 0.f, s2 = 0.f;
#pragma unroll
        for (int q = 0; q < 8; q++) { s += red[row * 8 + q]; s2 += red[256 + row * 8 + q]; }
        float mu = s * (1.f / 128.f);
        float var = s2 * (1.f / 128.f) - mu * mu;
        red[row * 8 + 0] = mu;
        red[row * 8 + 1] = rsqrtf(var + LN_EPS);
    }
    __syncthreads();
    {
        int row = tid >> 3, q = tid & 7;
        int g = m0 + row;
        if (g < N_NODES) {
            float mu = red[row * 8 + 0];
            float rstd = red[row * 8 + 1];
#pragma unroll
            for (int j = 0; j < 4; j++) {
                int col = q * 16 + j * 4;
                float4 v = *(float4*)(As + row * C_LDF + col);
                float4 gm = ((const float4*)gamma)[col >> 2];
                float4 bt = ((const float4*)beta)[col >> 2];
                v.x = (v.x - mu) * rstd * gm.x + bt.x;
                v.y = (v.y - mu) * rstd * gm.y + bt.y;
                v.z = (v.z - mu) * rstd * gm.z + bt.z;
                v.w = (v.w - mu) * rstd * gm.w + bt.w;
                *(float4*)(out + g * DIM + col) = v;
            }
        }
    }
}

// ---------------------------------------------------------------------------
extern "C" void kernel_launch(void* const* d_in, const int* in_sizes, int n_in,
                              void* d_out, int out_size) {
    const float* feat  = (const float*)d_in[0];
    const int*   src1  = (const int*)d_in[1];
    const int*   dst1  = (const int*)d_in[2];
    const int*   src2  = (const int*)d_in[3];
    const int*   dst2  = (const int*)d_in[4];
    const float* W1    = (const float*)d_in[5];
    const float* b1    = (const float*)d_in[6];
    const float* W2    = (const float*)d_in[7];
    const float* b2    = (const float*)d_in[8];
    const float* gamma = (const float*)d_in[9];
    const float* beta  = (const float*)d_in[10];
    float* out = (float*)d_out;

    cudaFuncSetAttribute(gemm_att_kernel, cudaFuncAttributeMaxDynamicSharedMemorySize, SMEM_BYTES);
    cudaFuncSetAttribute(gemm_ln_kernel,  cudaFuncAttributeMaxDynamicSharedMemorySize, SMEM_BYTES);

    zero_w_kernel<<<(4 * N_NODES + 255) / 256, 256>>>(W1, W2);
    degrees_kernel<<<(E_EDGES + 255) / 256, 256>>>(src1, dst1, src2, dst2);
    scan_norm_kernel<<<2 * N_TILES, 256>>>();
    scatter_convert_kernel<<<SCAT_BLOCKS + CONV_BLOCKS, 256>>>(src1, dst1, src2, dst2, feat);

    const int gemm_blocks = (N_NODES + TILE - 1) / TILE;   // 1563
    gemm_att_kernel<<<gemm_blocks, 256, SMEM_BYTES>>>(b1);
    gemm_ln_kernel<<<gemm_blocks, 256, SMEM_BYTES>>>(b2, gamma, beta, out);
}

// round 16
// speedup vs baseline: 1.2317x; 1.1014x over previous
#include <cuda_runtime.h>
#include <cuda_fp16.h>
#include <mma.h>
#include <math.h>

using namespace nvcuda;

#define N_NODES 50000
#define E_EDGES 800000
#define DIM 128
#define NHEAD 8
#define HDIM 16
#define LN_EPS 1e-5f
#define FULLMASK 0xFFFFFFFFu
#define TILE 32                     // gemm tile rows
#define BKT 64                      // bucket slots per dst node (max in-deg ~45)

// Scratch (static __device__ arrays: allocation-free per harness rules)
__device__ __half2 d_xh[N_NODES * 64];    // fp16 gather input, pass 1 (feat*norm_src1)
__device__ __half2 d_xh2[N_NODES * 64];   // fp16 gather input, pass 2 (attended*norm_src2)
__device__ int    d_deg[4 * N_NODES];     // [src1 | dst1 | src2 | dst2] degrees
__device__ int    d_bkt[2 * N_NODES * BKT];  // direct-bucket CSR [g1 | g2]
__device__ __half d_wh[2 * DIM * DIM];    // fp16 W1 | W2

__device__ __forceinline__ float deg_norm(int d) {
    return (d > 0) ? rsqrtf((float)d) : 0.f;
}

// ---------------------------------------------------------------------------
// Zero degrees + convert W1/W2 to fp16 (independent work).
// ---------------------------------------------------------------------------
__global__ void __launch_bounds__(256) zero_w_kernel(const float* __restrict__ W1,
                                                     const float* __restrict__ W2) {
    int i = blockIdx.x * 256 + threadIdx.x;
    if (i < 4 * N_NODES) d_deg[i] = 0;
    if (i < 2 * DIM * DIM / 4) {             // 8192 float4s
        const float* W = (i < 4096) ? W1 : W2;
        int li = (i < 4096) ? i : i - 4096;
        float4 v = ((const float4*)W)[li];
        __half2 h0 = __floats2half2_rn(v.x, v.y);
        __half2 h1 = __floats2half2_rn(v.z, v.w);
        uint2 st; st.x = *(unsigned*)&h0; st.y = *(unsigned*)&h1;
        *(uint2*)(d_wh + i * 4) = st;
    }
}

// ---------------------------------------------------------------------------
// Degrees + DIRECT bucket-CSR build. The dst atomic return is the bucket slot:
// d_bkt[dst*BKT + slot] = src. No scan, no scatter pass needed afterward.
// src counters remain non-returning (compile to RED).
// ---------------------------------------------------------------------------
__global__ void degrees_kernel(const int* __restrict__ s1, const int* __restrict__ t1,
                               const int* __restrict__ s2, const int* __restrict__ t2) {
    int i = blockIdx.x * blockDim.x + threadIdx.x;
    if (i >= E_EDGES) return;
    int a1 = s1[i], b1 = t1[i], a2 = s2[i], b2 = t2[i];
    atomicAdd(&d_deg[0 * N_NODES + a1], 1);
    atomicAdd(&d_deg[2 * N_NODES + a2], 1);
    int p1 = atomicAdd(&d_deg[1 * N_NODES + b1], 1);
    int p2 = atomicAdd(&d_deg[3 * N_NODES + b2], 1);
    d_bkt[b1 * BKT + p1] = a1;
    d_bkt[N_NODES * BKT + b2 * BKT + p2] = a2;
}

// ---------------------------------------------------------------------------
// feat * rsqrt(src1 degree) -> fp16 d_xh. Norm computed inline from d_deg.
// ---------------------------------------------------------------------------
#define CONV_BLOCKS ((N_NODES * 32 + 255) / 256) // 6250
__global__ void convert_kernel(const float* __restrict__ feat) {
    int i = blockIdx.x * 256 + threadIdx.x;
    if (i >= N_NODES * 32) return;
    int n = i >> 5, c4 = i & 31;
    float nm = deg_norm(d_deg[n]);              // src1 degree at offset 0
    float4 v = ((const float4*)feat)[i];
    __half2 h0 = __floats2half2_rn(v.x * nm, v.y * nm);
    __half2 h1 = __floats2half2_rn(v.z * nm, v.w * nm);
    uint2 st; st.x = *(unsigned*)&h0; st.y = *(unsigned*)&h1;
    *(uint2*)(d_xh + n * 64 + c4 * 2) = st;
}

// ---------------------------------------------------------------------------
// Fused gather + tensor-core GEMM. 32-row tiles, 5 blocks/SM.
// smem layout (bytes):
//   [0, 34816)       Ws_h: half[128][136]  -- later aliased by C (fp32 32x132)
//   [34816, 43520)   As_h: half[32][136]
//   [43520, 45568)   red:  float[512]
// ---------------------------------------------------------------------------
#define WS_H_OFF 0
#define AS_H_OFF 34816
#define RED_OFF  43520
#define SMEM_BYTES 45568
#define A_LDH 136
#define C_LDF 132

__device__ __forceinline__ void acc_half16(float4& a0, float4& a1, uint4 r) {
    __half2 h0 = *(__half2*)&r.x;
    __half2 h1 = *(__half2*)&r.y;
    __half2 h2 = *(__half2*)&r.z;
    __half2 h3 = *(__half2*)&r.w;
    float2 f0 = __half22float2(h0);
    float2 f1 = __half22float2(h1);
    float2 f2 = __half22float2(h2);
    float2 f3 = __half22float2(h3);
    a0.x += f0.x; a0.y += f0.y; a0.z += f1.x; a0.w += f1.y;
    a1.x += f2.x; a1.y += f2.y; a1.z += f3.x; a1.w += f3.y;
}

// fp16 depth-2 tree pre-add of 4 edges: (A+B)+(C+D), then fp32 accumulate.
__device__ __forceinline__ void acc_quad(float4& a0, float4& a1,
                                         uint4 rA, uint4 rB, uint4 rC, uint4 rD) {
    __half2 s0 = __hadd2(__hadd2(*(__half2*)&rA.x, *(__half2*)&rB.x),
                         __hadd2(*(__half2*)&rC.x, *(__half2*)&rD.x));
    __half2 s1 = __hadd2(__hadd2(*(__half2*)&rA.y, *(__half2*)&rB.y),
                         __hadd2(*(__half2*)&rC.y, *(__half2*)&rD.y));
    __half2 s2 = __hadd2(__hadd2(*(__half2*)&rA.z, *(__half2*)&rB.z),
                         __hadd2(*(__half2*)&rC.z, *(__half2*)&rD.z));
    __half2 s3 = __hadd2(__hadd2(*(__half2*)&rA.w, *(__half2*)&rB.w),
                         __hadd2(*(__half2*)&rC.w, *(__half2*)&rD.w));
    float2 f0 = __half22float2(s0);
    float2 f1 = __half22float2(s1);
    float2 f2 = __half22float2(s2);
    float2 f3 = __half22float2(s3);
    a0.x += f0.x; a0.y += f0.y; a0.z += f1.x; a0.w += f1.y;
    a1.x += f2.x; a1.y += f2.y; a1.z += f3.x; a1.w += f3.y;
}

__device__ __forceinline__ void gather_gemm_mainloop(char* smem, int graph, int w_off,
                                                     const __half2* __restrict__ base,
                                                     const float* __restrict__ bias,
                                                     int norm_off, int m0) {
    __half* Ws = (__half*)(smem + WS_H_OFF);
    __half* As = (__half*)(smem + AS_H_OFF);
    float*  C  = (float*)smem;
    int tid = threadIdx.x;

    // --- Phase 1: W fp16 (128x128) -> smem ld=136 (uint4 copies) ---
    const __half* Wh = d_wh + w_off;
#pragma unroll
    for (int j = 0; j < 8; j++) {
        int idx = j * 256 + tid;            // uint4 index, 2048 total
        int row = idx >> 4, c8 = idx & 15;  // 16 uint4 per row (128 halves)
        uint4 v = ((const uint4*)Wh)[idx];
        *(uint4*)(Ws + row * A_LDH + c8 * 8) = v;
    }

    // --- Phase 2: bucket-CSR gather directly into fp16 A smem ---
    int hw = tid >> 4;                       // half-warp 0..15
    int lane16 = tid & 15;
    unsigned hmask = 0xFFFFu << (tid & 16);
    int degseg = (graph == 0 ? 1 : 3) * N_NODES;
    const int* bkt = d_bkt + graph * N_NODES * BKT;

#pragma unroll
    for (int k = 0; k < 2; k++) {            // 2 rows per half-warp (32-row tile)
        int n_local = k * 16 + hw;
        int gnode = m0 + n_local;
        float4 a00 = make_float4(0.f,0.f,0.f,0.f), a01 = make_float4(0.f,0.f,0.f,0.f);
        float nm = 0.f;
        if (gnode < N_NODES) {
            int cnt = d_deg[degseg + gnode];
            nm = deg_norm(cnt);
            const int* row = bkt + gnode * BKT;
            for (int j0 = 0; j0 < cnt; j0 += 16) {
                int m = min(16, cnt - j0);
                int s_l = (lane16 < m) ? row[j0 + lane16] : 0;
                int jj = 0;
                for (; jj + 3 < m; jj += 4) {
                    int sA = __shfl_sync(hmask, s_l, jj,     16);
                    int sB = __shfl_sync(hmask, s_l, jj + 1, 16);
                    int sC = __shfl_sync(hmask, s_l, jj + 2, 16);
                    int sD = __shfl_sync(hmask, s_l, jj + 3, 16);
                    uint4 rA = *(const uint4*)(base + sA * 64 + lane16 * 4);
                    uint4 rB = *(const uint4*)(base + sB * 64 + lane16 * 4);
                    uint4 rC = *(const uint4*)(base + sC * 64 + lane16 * 4);
                    uint4 rD = *(const uint4*)(base + sD * 64 + lane16 * 4);
                    acc_quad(a00, a01, rA, rB, rC, rD);   // fp16 depth-2 tree pre-add
                }
                for (; jj < m; jj++) {
                    int sA = __shfl_sync(hmask, s_l, jj, 16);
                    uint4 rA = *(const uint4*)(base + sA * 64 + lane16 * 4);
                    acc_half16(a00, a01, rA);
                }
            }
        }
        __half2 h0 = __floats2half2_rn(a00.x * nm, a00.y * nm);
        __half2 h1 = __floats2half2_rn(a00.z * nm, a00.w * nm);
        __half2 h2 = __floats2half2_rn(a01.x * nm, a01.y * nm);
        __half2 h3 = __floats2half2_rn(a01.z * nm, a01.w * nm);
        uint4 st;
        st.x = *(unsigned int*)&h0;
        st.y = *(unsigned int*)&h1;
        st.z = *(unsigned int*)&h2;
        st.w = *(unsigned int*)&h3;
        *(uint4*)(As + n_local * A_LDH + lane16 * 8) = st;
    }
    __syncthreads();

    // --- Phase 3: wmma mainloop (8 warps: 2 row-groups x 4 col-groups) ---
    int wid = tid >> 5;
    int wm = wid & 1;        // 2 row-groups of 16
    int wn = wid >> 1;       // 4 col-groups of 32

    wmma::fragment<wmma::accumulator, 16, 16, 16, float> acc[2];
#pragma unroll
    for (int n = 0; n < 2; n++) wmma::fill_fragment(acc[n], 0.f);

#pragma unroll
    for (int k = 0; k < 8; k++) {
        wmma::fragment<wmma::matrix_a, 16, 16, 16, __half, wmma::row_major> fa;
        wmma::load_matrix_sync(fa, As + (wm * 16) * A_LDH + k * 16, A_LDH);
#pragma unroll
        for (int n = 0; n < 2; n++) {
            wmma::fragment<wmma::matrix_b, 16, 16, 16, __half, wmma::row_major> fb;
            wmma::load_matrix_sync(fb, Ws + (k * 16) * A_LDH + wn * 32 + n * 16, A_LDH);
            wmma::mma_sync(acc[n], fa, fb, acc[n]);
        }
    }
    __syncthreads();   // done reading Ws/As; C aliases Ws region

#pragma unroll
    for (int n = 0; n < 2; n++)
        wmma::store_matrix_sync(C + (wm * 16) * C_LDF + wn * 32 + n * 16,
                                acc[n], C_LDF, wmma::mem_row_major);
    __syncthreads();

    // bias + ReLU in place (32x128 = 1024 float4)
#pragma unroll
    for (int j = 0; j < 4; j++) {
        int idx = j * 256 + tid;
        int r = idx >> 5, c4 = idx & 31;
        float4 v = *(float4*)(C + r * C_LDF + c4 * 4);
        float4 bv = ((const float4*)bias)[c4];
        v.x = fmaxf(v.x + bv.x, 0.f);
        v.y = fmaxf(v.y + bv.y, 0.f);
        v.z = fmaxf(v.z + bv.z, 0.f);
        v.w = fmaxf(v.w + bv.w, 0.f);
        *(float4*)(C + r * C_LDF + c4 * 4) = v;
    }
    __syncthreads();
}

// gather(g1, from d_xh) + GEMM1 + attention + src2-norm prescale -> d_xh2 (fp16)
__global__ void __launch_bounds__(256, 5)
gemm_att_kernel(const float* __restrict__ bias) {
    extern __shared__ char smc[];
    float* As  = (float*)smc;                 // C tile (32 x 132)
    float* red = (float*)(smc + RED_OFF);
    int tid = threadIdx.x;
    int m0 = blockIdx.x * TILE;

    gather_gemm_mainloop(smc, 0, 0, d_xh, bias, 1 * N_NODES, m0);

    // scores: row = tid>>3 (0..31), head = tid&7
    {
        int row = tid >> 3, h = tid & 7;
        float s = 0.f;
#pragma unroll
        for (int c = 0; c < HDIM; c++) {
            float v = As[row * C_LDF + h * HDIM + c];
            s += v * v;
        }
        red[row * 8 + h] = s * 0.25f;          // / sqrt(HD)=4
    }
    __syncthreads();
    if ((tid & 7) == 0) {
        int row = tid >> 3;
        float sc[8], mx = -1e30f;
#pragma unroll
        for (int h = 0; h < 8; h++) { sc[h] = red[row * 8 + h]; mx = fmaxf(mx, sc[h]); }
        float sum = 0.f;
#pragma unroll
        for (int h = 0; h < 8; h++) { sc[h] = expf(sc[h] - mx); sum += sc[h]; }
        float inv = 1.f / sum;
#pragma unroll
        for (int h = 0; h < 8; h++) red[row * 8 + h] = sc[h] * inv;
    }
    __syncthreads();
    {
        int row = tid >> 3, q = tid & 7;       // q owns head q's 16 cols
        int g = m0 + row;
        if (g < N_NODES) {
            float p = red[row * 8 + q] * deg_norm(d_deg[2 * N_NODES + g]);  // src2 norm
#pragma unroll
            for (int j = 0; j < 4; j++) {
                int col = q * 16 + j * 4;
                float4 v = *(float4*)(As + row * C_LDF + col);
                __half2 h0 = __floats2half2_rn(v.x * p, v.y * p);
                __half2 h1 = __floats2half2_rn(v.z * p, v.w * p);
                uint2 st;
                st.x = *(unsigned int*)&h0;
                st.y = *(unsigned int*)&h1;
                *(uint2*)(d_xh2 + g * 64 + (col >> 1)) = st;   // double buffer
            }
        }
    }
}

// gather(g2, from d_xh2) + GEMM2 + LayerNorm -> out
__global__ void __launch_bounds__(256, 5)
gemm_ln_kernel(const float* __restrict__ bias,
               const float* __restrict__ gamma, const float* __restrict__ beta,
               float* __restrict__ out) {
    extern __shared__ char smc[];
    float* As  = (float*)smc;                 // C tile (32 x 132)
    float* red = (float*)(smc + RED_OFF);     // [0,256): sums, [256,512): sumsq
    int tid = threadIdx.x;
    int m0 = blockIdx.x * TILE;

    gather_gemm_mainloop(smc, 1, DIM * DIM, d_xh2, bias, 3 * N_NODES, m0);

    {
        int row = tid >> 3, q = tid & 7;
        float s = 0.f, s2 = 0.f;
#pragma unroll
        for (int c = 0; c < 16; c++) {
            float v = As[row * C_LDF + q * 16 + c];
            s += v; s2 += v * v;
        }
        red[tid] = s;
        red[256 + tid] = s2;
    }
    __syncthreads();
    if ((tid & 7) == 0) {
        int row = tid >> 3;
        float s = 0.f, s2 = 0.f;
#pragma unroll
        for (int q = 0; q < 8; q++) { s += red[row * 8 + q]; s2 += red[256 + row * 8 + q]; }
        float mu = s * (1.f / 128.f);
        float var = s2 * (1.f / 128.f) - mu * mu;
        red[row * 8 + 0] = mu;
        red[row * 8 + 1] = rsqrtf(var + LN_EPS);
    }
    __syncthreads();
    {
        int row = tid >> 3, q = tid & 7;
        int g = m0 + row;
        if (g < N_NODES) {
            float mu = red[row * 8 + 0];
            float rstd = red[row * 8 + 1];
#pragma unroll
            for (int j = 0; j < 4; j++) {
                int col = q * 16 + j * 4;
                float4 v = *(float4*)(As + row * C_LDF + col);
                float4 gm = ((const float4*)gamma)[col >> 2];
                float4 bt = ((const float4*)beta)[col >> 2];
                v.x = (v.x - mu) * rstd * gm.x + bt.x;
                v.y = (v.y - mu) * rstd * gm.y + bt.y;
                v.z = (v.z - mu) * rstd * gm.z + bt.z;
                v.w = (v.w - mu) * rstd * gm.w + bt.w;
                *(float4*)(out + g * DIM + col) = v;
            }
        }
    }
}

// ---------------------------------------------------------------------------
extern "C" void kernel_launch(void* const* d_in, const int* in_sizes, int n_in,
                              void* d_out, int out_size) {
    const float* feat  = (const float*)d_in[0];
    const int*   src1  = (const int*)d_in[1];
    const int*   dst1  = (const int*)d_in[2];
    const int*   src2  = (const int*)d_in[3];
    const int*   dst2  = (const int*)d_in[4];
    const float* W1    = (const float*)d_in[5];
    const float* b1    = (const float*)d_in[6];
    const float* W2    = (const float*)d_in[7];
    const float* b2    = (const float*)d_in[8];
    const float* gamma = (const float*)d_in[9];
    const float* beta  = (const float*)d_in[10];
    float* out = (float*)d_out;

    cudaFuncSetAttribute(gemm_att_kernel, cudaFuncAttributeMaxDynamicSharedMemorySize, SMEM_BYTES);
    cudaFuncSetAttribute(gemm_ln_kernel,  cudaFuncAttributeMaxDynamicSharedMemorySize, SMEM_BYTES);

    zero_w_kernel<<<(4 * N_NODES + 255) / 256, 256>>>(W1, W2);
    degrees_kernel<<<(E_EDGES + 255) / 256, 256>>>(src1, dst1, src2, dst2);
    convert_kernel<<<CONV_BLOCKS, 256>>>(feat);

    const int gemm_blocks = (N_NODES + TILE - 1) / TILE;   // 1563
    gemm_att_kernel<<<gemm_blocks, 256, SMEM_BYTES>>>(b1);
    gemm_ln_kernel<<<gemm_blocks, 256, SMEM_BYTES>>>(b2, gamma, beta, out);
}

// round 17
// speedup vs baseline: 1.2498x; 1.0147x over previous
#include <cuda_runtime.h>
#include <cuda_fp16.h>
#include <mma.h>
#include <math.h>

using namespace nvcuda;

#define N_NODES 50000
#define E_EDGES 800000
#define DIM 128
#define NHEAD 8
#define HDIM 16
#define LN_EPS 1e-5f
#define FULLMASK 0xFFFFFFFFu
#define TILE 32                     // gemm tile rows
#define BKT 64                      // bucket slots per dst node (max in-deg ~45)

// Scratch (static __device__ arrays: allocation-free per harness rules)
__device__ __half2 d_xh[N_NODES * 64];    // fp16 gather input, pass 1 (feat*norm_src1)
__device__ __half2 d_xh2[N_NODES * 64];   // fp16 gather input, pass 2 (attended*norm_src2)
__device__ int    d_deg[4 * N_NODES];     // [src1 | dst1 | src2 | dst2] degrees
__device__ int    d_bkt[2 * N_NODES * BKT];  // direct-bucket CSR [g1 | g2]
__device__ __half d_wh[2 * DIM * DIM];    // fp16 W1 | W2

__device__ __forceinline__ float deg_norm(int d) {
    return (d > 0) ? rsqrtf((float)d) : 0.f;
}

// ---------------------------------------------------------------------------
// Zero degrees + convert W1/W2 to fp16 (independent work).
// ---------------------------------------------------------------------------
__global__ void __launch_bounds__(256) zero_w_kernel(const float* __restrict__ W1,
                                                     const float* __restrict__ W2) {
    int i = blockIdx.x * 256 + threadIdx.x;
    if (i < 4 * N_NODES) d_deg[i] = 0;
    if (i < 2 * DIM * DIM / 4) {             // 8192 float4s
        const float* W = (i < 4096) ? W1 : W2;
        int li = (i < 4096) ? i : i - 4096;
        float4 v = ((const float4*)W)[li];
        __half2 h0 = __floats2half2_rn(v.x, v.y);
        __half2 h1 = __floats2half2_rn(v.z, v.w);
        uint2 st; st.x = *(unsigned*)&h0; st.y = *(unsigned*)&h1;
        *(uint2*)(d_wh + i * 4) = st;
    }
}

// ---------------------------------------------------------------------------
// Degrees + DIRECT bucket-CSR build. The dst atomic return is the bucket slot:
// d_bkt[dst*BKT + slot] = src. No scan, no scatter pass needed afterward.
// ---------------------------------------------------------------------------
__global__ void degrees_kernel(const int* __restrict__ s1, const int* __restrict__ t1,
                               const int* __restrict__ s2, const int* __restrict__ t2) {
    int i = blockIdx.x * blockDim.x + threadIdx.x;
    if (i >= E_EDGES) return;
    int a1 = s1[i], b1 = t1[i], a2 = s2[i], b2 = t2[i];
    atomicAdd(&d_deg[0 * N_NODES + a1], 1);
    atomicAdd(&d_deg[2 * N_NODES + a2], 1);
    int p1 = atomicAdd(&d_deg[1 * N_NODES + b1], 1);
    int p2 = atomicAdd(&d_deg[3 * N_NODES + b2], 1);
    d_bkt[b1 * BKT + p1] = a1;
    d_bkt[N_NODES * BKT + b2 * BKT + p2] = a2;
}

// ---------------------------------------------------------------------------
// feat * rsqrt(src1 degree) -> fp16 d_xh. Norm computed inline from d_deg.
// ---------------------------------------------------------------------------
#define CONV_BLOCKS ((N_NODES * 32 + 255) / 256) // 6250
__global__ void convert_kernel(const float* __restrict__ feat) {
    int i = blockIdx.x * 256 + threadIdx.x;
    if (i >= N_NODES * 32) return;
    int n = i >> 5, c4 = i & 31;
    float nm = deg_norm(d_deg[n]);              // src1 degree at offset 0
    float4 v = ((const float4*)feat)[i];
    __half2 h0 = __floats2half2_rn(v.x * nm, v.y * nm);
    __half2 h1 = __floats2half2_rn(v.z * nm, v.w * nm);
    uint2 st; st.x = *(unsigned*)&h0; st.y = *(unsigned*)&h1;
    *(uint2*)(d_xh + n * 64 + c4 * 2) = st;
}

// ---------------------------------------------------------------------------
// Fused gather + tensor-core GEMM. 32-row tiles, 5 blocks/SM.
// smem layout (bytes):
//   [0, 34816)       Ws_h: half[128][136]  -- later aliased by C (fp32 32x132)
//   [34816, 43520)   As_h: half[32][136]
//   [43520, 45568)   red:  float[512]
// ---------------------------------------------------------------------------
#define WS_H_OFF 0
#define AS_H_OFF 34816
#define RED_OFF  43520
#define SMEM_BYTES 45568
#define A_LDH 136
#define C_LDF 132

__device__ __forceinline__ void acc_half16(float4& a0, float4& a1, uint4 r) {
    __half2 h0 = *(__half2*)&r.x;
    __half2 h1 = *(__half2*)&r.y;
    __half2 h2 = *(__half2*)&r.z;
    __half2 h3 = *(__half2*)&r.w;
    float2 f0 = __half22float2(h0);
    float2 f1 = __half22float2(h1);
    float2 f2 = __half22float2(h2);
    float2 f3 = __half22float2(h3);
    a0.x += f0.x; a0.y += f0.y; a0.z += f1.x; a0.w += f1.y;
    a1.x += f2.x; a1.y += f2.y; a1.z += f3.x; a1.w += f3.y;
}

// fp16 depth-2 tree pre-add of 4 edges: (A+B)+(C+D), then fp32 accumulate.
__device__ __forceinline__ void acc_quad(float4& a0, float4& a1,
                                         uint4 rA, uint4 rB, uint4 rC, uint4 rD) {
    __half2 s0 = __hadd2(__hadd2(*(__half2*)&rA.x, *(__half2*)&rB.x),
                         __hadd2(*(__half2*)&rC.x, *(__half2*)&rD.x));
    __half2 s1 = __hadd2(__hadd2(*(__half2*)&rA.y, *(__half2*)&rB.y),
                         __hadd2(*(__half2*)&rC.y, *(__half2*)&rD.y));
    __half2 s2 = __hadd2(__hadd2(*(__half2*)&rA.z, *(__half2*)&rB.z),
                         __hadd2(*(__half2*)&rC.z, *(__half2*)&rD.z));
    __half2 s3 = __hadd2(__hadd2(*(__half2*)&rA.w, *(__half2*)&rB.w),
                         __hadd2(*(__half2*)&rC.w, *(__half2*)&rD.w));
    float2 f0 = __half22float2(s0);
    float2 f1 = __half22float2(s1);
    float2 f2 = __half22float2(s2);
    float2 f3 = __half22float2(s3);
    a0.x += f0.x; a0.y += f0.y; a0.z += f1.x; a0.w += f1.y;
    a1.x += f2.x; a1.y += f2.y; a1.z += f3.x; a1.w += f3.y;
}

__device__ __forceinline__ void gather_gemm_mainloop(char* smem, int graph, int w_off,
                                                     const __half2* __restrict__ base,
                                                     const float* __restrict__ bias,
                                                     int norm_off, int m0) {
    __half* Ws = (__half*)(smem + WS_H_OFF);
    __half* As = (__half*)(smem + AS_H_OFF);
    float*  C  = (float*)smem;
    int tid = threadIdx.x;

    // --- Phase 1: W fp16 (128x128) -> smem ld=136 (uint4 copies) ---
    const __half* Wh = d_wh + w_off;
#pragma unroll
    for (int j = 0; j < 8; j++) {
        int idx = j * 256 + tid;            // uint4 index, 2048 total
        int row = idx >> 4, c8 = idx & 15;  // 16 uint4 per row (128 halves)
        uint4 v = ((const uint4*)Wh)[idx];
        *(uint4*)(Ws + row * A_LDH + c8 * 8) = v;
    }

    // --- Phase 2: bucket-CSR gather directly into fp16 A smem ---
    // Indices fetched via lane-uniform int4 loads (L1 broadcast) — no shuffles.
    int hw = tid >> 4;                       // half-warp 0..15
    int lane16 = tid & 15;
    int degseg = (graph == 0 ? 1 : 3) * N_NODES;
    const int* bkt = d_bkt + graph * N_NODES * BKT;
    const __half2* lanebase = base + lane16 * 4;   // lane's 8B column offset

#pragma unroll
    for (int k = 0; k < 2; k++) {            // 2 rows per half-warp (32-row tile)
        int n_local = k * 16 + hw;
        int gnode = m0 + n_local;
        float4 a00 = make_float4(0.f,0.f,0.f,0.f), a01 = make_float4(0.f,0.f,0.f,0.f);
        float nm = 0.f;
        if (gnode < N_NODES) {
            int cnt = d_deg[degseg + gnode];
            nm = deg_norm(cnt);
            const int* row = bkt + gnode * BKT;
            int jj = 0;
            for (; jj + 3 < cnt; jj += 4) {
                int4 q = *(const int4*)(row + jj);      // uniform: same addr all lanes
                uint4 rA = *(const uint4*)(lanebase + q.x * 64);
                uint4 rB = *(const uint4*)(lanebase + q.y * 64);
                uint4 rC = *(const uint4*)(lanebase + q.z * 64);
                uint4 rD = *(const uint4*)(lanebase + q.w * 64);
                acc_quad(a00, a01, rA, rB, rC, rD);     // fp16 depth-2 tree pre-add
            }
            for (; jj < cnt; jj++) {
                int s = row[jj];                        // uniform scalar load
                uint4 rA = *(const uint4*)(lanebase + s * 64);
                acc_half16(a00, a01, rA);
            }
        }
        __half2 h0 = __floats2half2_rn(a00.x * nm, a00.y * nm);
        __half2 h1 = __floats2half2_rn(a00.z * nm, a00.w * nm);
        __half2 h2 = __floats2half2_rn(a01.x * nm, a01.y * nm);
        __half2 h3 = __floats2half2_rn(a01.z * nm, a01.w * nm);
        uint4 st;
        st.x = *(unsigned int*)&h0;
        st.y = *(unsigned int*)&h1;
        st.z = *(unsigned int*)&h2;
        st.w = *(unsigned int*)&h3;
        *(uint4*)(As + n_local * A_LDH + lane16 * 8) = st;
    }
    __syncthreads();

    // --- Phase 3: wmma mainloop (8 warps: 2 row-groups x 4 col-groups) ---
    int wid = tid >> 5;
    int wm = wid & 1;        // 2 row-groups of 16
    int wn = wid >> 1;       // 4 col-groups of 32

    wmma::fragment<wmma::accumulator, 16, 16, 16, float> acc[2];
#pragma unroll
    for (int n = 0; n < 2; n++) wmma::fill_fragment(acc[n], 0.f);

#pragma unroll
    for (int k = 0; k < 8; k++) {
        wmma::fragment<wmma::matrix_a, 16, 16, 16, __half, wmma::row_major> fa;
        wmma::load_matrix_sync(fa, As + (wm * 16) * A_LDH + k * 16, A_LDH);
#pragma unroll
        for (int n = 0; n < 2; n++) {
            wmma::fragment<wmma::matrix_b, 16, 16, 16, __half, wmma::row_major> fb;
            wmma::load_matrix_sync(fb, Ws + (k * 16) * A_LDH + wn * 32 + n * 16, A_LDH);
            wmma::mma_sync(acc[n], fa, fb, acc[n]);
        }
    }
    __syncthreads();   // done reading Ws/As; C aliases Ws region

#pragma unroll
    for (int n = 0; n < 2; n++)
        wmma::store_matrix_sync(C + (wm * 16) * C_LDF + wn * 32 + n * 16,
                                acc[n], C_LDF, wmma::mem_row_major);
    __syncthreads();

    // bias + ReLU in place (32x128 = 1024 float4)
#pragma unroll
    for (int j = 0; j < 4; j++) {
        int idx = j * 256 + tid;
        int r = idx >> 5, c4 = idx & 31;
        float4 v = *(float4*)(C + r * C_LDF + c4 * 4);
        float4 bv = ((const float4*)bias)[c4];
        v.x = fmaxf(v.x + bv.x, 0.f);
        v.y = fmaxf(v.y + bv.y, 0.f);
        v.z = fmaxf(v.z + bv.z, 0.f);
        v.w = fmaxf(v.w + bv.w, 0.f);
        *(float4*)(C + r * C_LDF + c4 * 4) = v;
    }
    __syncthreads();
}

// gather(g1, from d_xh) + GEMM1 + attention + src2-norm prescale -> d_xh2 (fp16)
__global__ void __launch_bounds__(256, 5)
gemm_att_kernel(const float* __restrict__ bias) {
    extern __shared__ char smc[];
    float* As  = (float*)smc;                 // C tile (32 x 132)
    float* red = (float*)(smc + RED_OFF);
    int tid = threadIdx.x;
    int m0 = blockIdx.x * TILE;

    gather_gemm_mainloop(smc, 0, 0, d_xh, bias, 1 * N_NODES, m0);

    // scores: row = tid>>3 (0..31), head = tid&7
    {
        int row = tid >> 3, h = tid & 7;
        float s = 0.f;
#pragma unroll
        for (int c = 0; c < HDIM; c++) {
            float v = As[row * C_LDF + h * HDIM + c];
            s += v * v;
        }
        red[row * 8 + h] = s * 0.25f;          // / sqrt(HD)=4
    }
    __syncthreads();
    if ((tid & 7) == 0) {
        int row = tid >> 3;
        float sc[8], mx = -1e30f;
#pragma unroll
        for (int h = 0; h < 8; h++) { sc[h] = red[row * 8 + h]; mx = fmaxf(mx, sc[h]); }
        float sum = 0.f;
#pragma unroll
        for (int h = 0; h < 8; h++) { sc[h] = expf(sc[h] - mx); sum += sc[h]; }
        float inv = 1.f / sum;
#pragma unroll
        for (int h = 0; h < 8; h++) red[row * 8 + h] = sc[h] * inv;
    }
    __syncthreads();
    {
        int row = tid >> 3, q = tid & 7;       // q owns head q's 16 cols
        int g = m0 + row;
        if (g < N_NODES) {
            float p = red[row * 8 + q] * deg_norm(d_deg[2 * N_NODES + g]);  // src2 norm
#pragma unroll
            for (int j = 0; j < 4; j++) {
                int col = q * 16 + j * 4;
                float4 v = *(float4*)(As + row * C_LDF + col);
                __half2 h0 = __floats2half2_rn(v.x * p, v.y * p);
                __half2 h1 = __floats2half2_rn(v.z * p, v.w * p);
                uint2 st;
                st.x = *(unsigned int*)&h0;
                st.y = *(unsigned int*)&h1;
                *(uint2*)(d_xh2 + g * 64 + (col >> 1)) = st;   // double buffer
            }
        }
    }
}

// gather(g2, from d_xh2) + GEMM2 + LayerNorm -> out
__global__ void __launch_bounds__(256, 5)
gemm_ln_kernel(const float* __restrict__ bias,
               const float* __restrict__ gamma, const float* __restrict__ beta,
               float* __restrict__ out) {
    extern __shared__ char smc[];
    float* As  = (float*)smc;                 // C tile (32 x 132)
    float* red = (float*)(smc + RED_OFF);     // [0,256): sums, [256,512): sumsq
    int tid = threadIdx.x;
    int m0 = blockIdx.x * TILE;

    gather_gemm_mainloop(smc, 1, DIM * DIM, d_xh2, bias, 3 * N_NODES, m0);

    {
        int row = tid >> 3, q = tid & 7;
        float s = 0.f, s2 = 0.f;
#pragma unroll
        for (int c = 0; c < 16; c++) {
            float v = As[row * C_LDF + q * 16 + c];
            s += v; s2 += v * v;
        }
        red[tid] = s;
        red[256 + tid] = s2;
    }
    __syncthreads();
    if ((tid & 7) == 0) {
        int row = tid >> 3;
        float s = 0.f, s2 = 0.f;
#pragma unroll
        for (int q = 0; q < 8; q++) { s += red[row * 8 + q]; s2 += red[256 + row * 8 + q]; }
        float mu = s * (1.f / 128.f);
        float var = s2 * (1.f / 128.f) - mu * mu;
        red[row * 8 + 0] = mu;
        red[row * 8 + 1] = rsqrtf(var + LN_EPS);
    }
    __syncthreads();
    {
        int row = tid >> 3, q = tid & 7;
        int g = m0 + row;
        if (g < N_NODES) {
            float mu = red[row * 8 + 0];
            float rstd = red[row * 8 + 1];
#pragma unroll
            for (int j = 0; j < 4; j++) {
                int col = q * 16 + j * 4;
                float4 v = *(float4*)(As + row * C_LDF + col);
                float4 gm = ((const float4*)gamma)[col >> 2];
                float4 bt = ((const float4*)beta)[col >> 2];
                v.x = (v.x - mu) * rstd * gm.x + bt.x;
                v.y = (v.y - mu) * rstd * gm.y + bt.y;
                v.z = (v.z - mu) * rstd * gm.z + bt.z;
                v.w = (v.w - mu) * rstd * gm.w + bt.w;
                *(float4*)(out + g * DIM + col) = v;
            }
        }
    }
}

// ---------------------------------------------------------------------------
extern "C" void kernel_launch(void* const* d_in, const int* in_sizes, int n_in,
                              void* d_out, int out_size) {
    const float* feat  = (const float*)d_in[0];
    const int*   src1  = (const int*)d_in[1];
    const int*   dst1  = (const int*)d_in[2];
    const int*   src2  = (const int*)d_in[3];
    const int*   dst2  = (const int*)d_in[4];
    const float* W1    = (const float*)d_in[5];
    const float* b1    = (const float*)d_in[6];
    const float* W2    = (const float*)d_in[7];
    const float* b2    = (const float*)d_in[8];
    const float* gamma = (const float*)d_in[9];
    const float* beta  = (const float*)d_in[10];
    float* out = (float*)d_out;

    cudaFuncSetAttribute(gemm_att_kernel, cudaFuncAttributeMaxDynamicSharedMemorySize, SMEM_BYTES);
    cudaFuncSetAttribute(gemm_ln_kernel,  cudaFuncAttributeMaxDynamicSharedMemorySize, SMEM_BYTES);

    zero_w_kernel<<<(4 * N_NODES + 255) / 256, 256>>>(W1, W2);
    degrees_kernel<<<(E_EDGES + 255) / 256, 256>>>(src1, dst1, src2, dst2);
    convert_kernel<<<CONV_BLOCKS, 256>>>(feat);

    const int gemm_blocks = (N_NODES + TILE - 1) / TILE;   // 1563
    gemm_att_kernel<<<gemm_blocks, 256, SMEM_BYTES>>>(b1);
    gemm_ln_kernel<<<gemm_blocks, 256, SMEM_BYTES>>>(b2, gamma, beta, out);
}